// round 1
// baseline (speedup 1.0000x reference)
#include <cuda_runtime.h>

// ---------------- problem constants ----------------
// B=4, S=8192, F=1024, H=16, D=64; M = B*S = 32768
// reshape mapping (verified): h = s>>9, n = (s&511)*16 + (f>>6), d = f&63
//   => flat index within q/k/v buffers:  b*S*F + h*(512*1024) + n*64 + d
static constexpr int Bb = 4, Ss = 8192, Ff = 1024, Hh = 16, Dd = 64;
static constexpr int Mm = Bb * Ss;              // 32768
static constexpr int Kk = 1024, Nn = 1024;      // GEMM K and N
static constexpr long QELEMS = (long)Mm * Ff;   // 33554432
static constexpr int NCHUNK = 16;               // split-n chunks for p_attn
static constexpr int ROWS_PER_CHUNK = 8192 / NCHUNK;  // 512

// ---------------- scratch (device globals; no allocs allowed) ----------------
__device__ float gQ[33554432];
__device__ float gK[33554432];
__device__ float gV[33554432];
__device__ float gPpart[(long)NCHUNK * 64 * 4096];   // 16 MB partials

// ---------------- GEMM: C[M,N] = A[M,K] @ W[K,N]  (fp32 SIMT, 128x128x16) ----
#define BM 128
#define BN 128
#define BK 16

__global__ __launch_bounds__(256, 2)
void gemm_kernel(const float* __restrict__ A, const float* __restrict__ W, int which)
{
    __shared__ float As[BK][BM];
    __shared__ float Bs[BK][BN];

    float* C = (which == 0) ? gQ : (which == 1) ? gK : gV;

    const int bx = blockIdx.x;          // N tile: 0..7
    const int by = blockIdx.y;          // M tile: 0..255
    const int t  = threadIdx.x;
    const int row0 = by * BM;
    const int col0 = bx * BN;
    const int tx = t & 15;              // 0..15
    const int ty = t >> 4;              // 0..15

    const float* Aptr = A + (long)row0 * Kk;
    const float* Wptr = W + col0;

    float acc[8][8];
#pragma unroll
    for (int i = 0; i < 8; i++)
#pragma unroll
        for (int j = 0; j < 8; j++) acc[i][j] = 0.f;

    for (int k0 = 0; k0 < Kk; k0 += BK) {
        // load A tile (128 x 16), store transposed As[k][m]
#pragma unroll
        for (int i = 0; i < 2; i++) {
            int idx = t + i * 256;              // 0..511
            int ar = idx >> 2;                  // 0..127
            int aq = (idx & 3) * 4;             // 0,4,8,12
            float4 v = *(const float4*)(Aptr + (long)ar * Kk + k0 + aq);
            As[aq + 0][ar] = v.x;
            As[aq + 1][ar] = v.y;
            As[aq + 2][ar] = v.z;
            As[aq + 3][ar] = v.w;
        }
        // load B tile (16 x 128)
#pragma unroll
        for (int i = 0; i < 2; i++) {
            int idx = t + i * 256;
            int br = idx >> 5;                  // 0..15
            int bq = (idx & 31) * 4;            // 0..124
            *(float4*)(&Bs[br][bq]) = *(const float4*)(Wptr + (long)(k0 + br) * Nn + bq);
        }
        __syncthreads();

#pragma unroll
        for (int k = 0; k < BK; k++) {
            float a[8], b[8];
            *(float4*)(a)     = *(const float4*)(&As[k][ty * 4]);
            *(float4*)(a + 4) = *(const float4*)(&As[k][64 + ty * 4]);
            *(float4*)(b)     = *(const float4*)(&Bs[k][tx * 4]);
            *(float4*)(b + 4) = *(const float4*)(&Bs[k][64 + tx * 4]);
#pragma unroll
            for (int i = 0; i < 8; i++)
#pragma unroll
                for (int j = 0; j < 8; j++)
                    acc[i][j] += a[i] * b[j];
        }
        __syncthreads();
    }

    // epilogue
#pragma unroll
    for (int i = 0; i < 8; i++) {
        int rl = (i < 4) ? (ty * 4 + i) : (64 + ty * 4 + (i - 4));
        long ro = (long)(row0 + rl) * Nn + col0;
        float4 v0 = make_float4(acc[i][0], acc[i][1], acc[i][2], acc[i][3]);
        float4 v1 = make_float4(acc[i][4], acc[i][5], acc[i][6], acc[i][7]);
        *(float4*)(C + ro + tx * 4)      = v0;
        *(float4*)(C + ro + 64 + tx * 4) = v1;
    }
}

// ---------------- p_attn partials: LN(K)^T LN(V) over an n-chunk -------------
__global__ __launch_bounds__(256)
void pattn_partial_kernel(const float* __restrict__ lnk_s, const float* __restrict__ lnk_b,
                          const float* __restrict__ lnv_s, const float* __restrict__ lnv_b)
{
    const int bh = blockIdx.x;           // 0..63
    const int chunk = blockIdx.y;        // 0..NCHUNK-1
    const int b = bh >> 4, h = bh & 15;
    const int n0 = chunk * ROWS_PER_CHUNK;
    const long base = (long)b * (Ss * Ff) + (long)h * (512 * 1024);

    __shared__ float ks[16][64];
    __shared__ float vs[16][64];
    __shared__ float sks[64], skb[64], svs[64], svb[64];

    const int t = threadIdx.x;
    const int warp = t >> 5, lane = t & 31;

    if (t < 64) {
        sks[t] = lnk_s[h * 64 + t];
        skb[t] = lnk_b[h * 64 + t];
        svs[t] = lnv_s[h * 64 + t];
        svb[t] = lnv_b[h * 64 + t];
    }

    float acc[4][4];
#pragma unroll
    for (int i = 0; i < 4; i++)
#pragma unroll
        for (int j = 0; j < 4; j++) acc[i][j] = 0.f;

    const int td = (t >> 4) * 4;   // d offset 0..60
    const int te = (t & 15) * 4;   // e offset 0..60

    for (int r0 = 0; r0 < ROWS_PER_CHUNK; r0 += 16) {
        __syncthreads();   // smem reuse guard (also orders scale loads on iter 0)
        // stage 16 rows with LayerNorm; warp w handles rows 2w, 2w+1
#pragma unroll
        for (int rr = 0; rr < 2; rr++) {
            int r = 2 * warp + rr;
            long off = base + (long)(n0 + r0 + r) * 64;

            float kx0 = gK[off + lane];
            float kx1 = gK[off + 32 + lane];
            float vx0 = gV[off + lane];
            float vx1 = gV[off + 32 + lane];

            float ksum = kx0 + kx1, ksq = kx0 * kx0 + kx1 * kx1;
            float vsum = vx0 + vx1, vsq = vx0 * vx0 + vx1 * vx1;
#pragma unroll
            for (int o = 16; o > 0; o >>= 1) {
                ksum += __shfl_xor_sync(0xffffffffu, ksum, o);
                ksq  += __shfl_xor_sync(0xffffffffu, ksq, o);
                vsum += __shfl_xor_sync(0xffffffffu, vsum, o);
                vsq  += __shfl_xor_sync(0xffffffffu, vsq, o);
            }
            float kmu = ksum * (1.f / 64.f);
            float kvar = ksq * (1.f / 64.f) - kmu * kmu;
            float krs = rsqrtf(kvar + 1e-6f);
            float vmu = vsum * (1.f / 64.f);
            float vvar = vsq * (1.f / 64.f) - vmu * vmu;
            float vrs = rsqrtf(vvar + 1e-6f);

            ks[r][lane]      = (kx0 - kmu) * krs * sks[lane]      + skb[lane];
            ks[r][lane + 32] = (kx1 - kmu) * krs * sks[lane + 32] + skb[lane + 32];
            vs[r][lane]      = (vx0 - vmu) * vrs * svs[lane]      + svb[lane];
            vs[r][lane + 32] = (vx1 - vmu) * vrs * svs[lane + 32] + svb[lane + 32];
        }
        __syncthreads();

#pragma unroll
        for (int r = 0; r < 16; r++) {
            float4 kq = *(const float4*)(&ks[r][td]);
            float4 vq = *(const float4*)(&vs[r][te]);
            float ka[4] = {kq.x, kq.y, kq.z, kq.w};
            float va[4] = {vq.x, vq.y, vq.z, vq.w};
#pragma unroll
            for (int i = 0; i < 4; i++)
#pragma unroll
                for (int j = 0; j < 4; j++)
                    acc[i][j] += ka[i] * va[j];
        }
    }

    float* p = gPpart + ((long)chunk * 64 + bh) * 4096;
#pragma unroll
    for (int i = 0; i < 4; i++)
#pragma unroll
        for (int j = 0; j < 4; j++)
            p[(td + i) * 64 + (te + j)] = acc[i][j];
}

// ---------------- p_attn reduce: sum partials / N, write to d_out tail -------
__global__ void pattn_reduce_kernel(float* __restrict__ pout)
{
    int i = blockIdx.x * blockDim.x + threadIdx.x;   // 0..262143
    if (i >= 64 * 4096) return;
    int bh = i >> 12;
    int idx = i & 4095;
    float s = 0.f;
#pragma unroll
    for (int c = 0; c < NCHUNK; c++)
        s += gPpart[((long)c * 64 + bh) * 4096 + idx];
    pout[i] = s * (1.f / 8192.f);
}

// ---------------- x = Q @ P per (b,h), write att_output ----------------------
__global__ __launch_bounds__(256)
void out_kernel(const float* __restrict__ pattn, float* __restrict__ out)
{
    const int bh = blockIdx.y;
    const int b = bh >> 4, h = bh & 15;
    const int n0 = blockIdx.x * 64;

    __shared__ float ps[64][64];
    __shared__ float qs[64][68];   // padded: stride 68 floats = 272B (16B aligned)

    const int t = threadIdx.x;
    const float* P = pattn + (long)bh * 4096;
    for (int i = t; i < 4096; i += 256)
        ps[i >> 6][i & 63] = P[i];

    const long base = (long)b * (Ss * Ff) + (long)h * 524288 + (long)n0 * 64;
#pragma unroll
    for (int it = 0; it < 4; it++) {
        int i = t * 4 + it * 1024;          // multiple of 4
        *(float4*)(&qs[i >> 6][i & 63]) = *(const float4*)(gQ + base + i);
    }
    __syncthreads();

    const int r  = t >> 2;            // row within tile 0..63
    const int eg = (t & 3) * 16;      // 16-wide e group

    float acc[16];
#pragma unroll
    for (int j = 0; j < 16; j++) acc[j] = 0.f;

#pragma unroll
    for (int d = 0; d < 64; d++) {
        float q = qs[r][d];
#pragma unroll
        for (int j4 = 0; j4 < 4; j4++) {
            float4 pv = *(const float4*)(&ps[d][eg + j4 * 4]);
            acc[j4 * 4 + 0] += q * pv.x;
            acc[j4 * 4 + 1] += q * pv.y;
            acc[j4 * 4 + 2] += q * pv.z;
            acc[j4 * 4 + 3] += q * pv.w;
        }
    }

    float* o = out + base + (long)r * 64 + eg;
#pragma unroll
    for (int j4 = 0; j4 < 4; j4++)
        *(float4*)(o + j4 * 4) = make_float4(acc[j4 * 4 + 0], acc[j4 * 4 + 1],
                                             acc[j4 * 4 + 2], acc[j4 * 4 + 3]);
}

// ---------------- launch ----------------------------------------------------
extern "C" void kernel_launch(void* const* d_in, const int* in_sizes, int n_in,
                              void* d_out, int out_size)
{
    (void)in_sizes; (void)n_in; (void)out_size;
    const float* query = (const float*)d_in[0];
    const float* key   = (const float*)d_in[1];
    const float* value = (const float*)d_in[2];
    const float* Wq    = (const float*)d_in[3];
    const float* Wk    = (const float*)d_in[4];
    const float* Wv    = (const float*)d_in[5];
    const float* lnk_s = (const float*)d_in[6];
    const float* lnk_b = (const float*)d_in[7];
    const float* lnv_s = (const float*)d_in[8];
    const float* lnv_b = (const float*)d_in[9];

    float* out = (float*)d_out;                 // att_output: 33554432 floats
    float* pout = out + QELEMS;                 // p_attn: 262144 floats

    dim3 gemm_grid(Nn / BN, Mm / BM);           // (8, 256)
    gemm_kernel<<<gemm_grid, 256>>>(query, Wq, 0);
    gemm_kernel<<<gemm_grid, 256>>>(key,   Wk, 1);
    gemm_kernel<<<gemm_grid, 256>>>(value, Wv, 2);

    dim3 pgrid(64, NCHUNK);
    pattn_partial_kernel<<<pgrid, 256>>>(lnk_s, lnk_b, lnv_s, lnv_b);

    pattn_reduce_kernel<<<(64 * 4096 + 255) / 256, 256>>>(pout);

    dim3 ogrid(8192 / 64, 64);
    out_kernel<<<ogrid, 256>>>(pout, out);
}

// round 3
// speedup vs baseline: 2.1424x; 2.1424x over previous
#include <cuda_runtime.h>
#include <cuda_bf16.h>
#include <cstdint>

// ---------------- problem constants ----------------
static constexpr int Bb = 4, Ss = 8192, Ff = 1024, Hh = 16, Dd = 64;
static constexpr int Mm = Bb * Ss;              // 32768
static constexpr int Kk = 1024, Nn = 1024;
static constexpr long QELEMS = (long)Mm * Ff;   // 33554432
static constexpr int NCHUNK = 16;
static constexpr int ROWS_PER_CHUNK = 8192 / NCHUNK;  // 512

// ---------------- scratch (device globals) ----------------
__device__ float gQ[33554432];
__device__ float gK[33554432];
__device__ float gV[33554432];
__device__ float gPpart[(long)NCHUNK * 64 * 4096];
__device__ __nv_bfloat16 gAhi[3L * 33554432];
__device__ __nv_bfloat16 gAlo[3L * 33554432];
__device__ __nv_bfloat16 gWthi[3L * 1048576];   // W^T: [n][k], k contiguous
__device__ __nv_bfloat16 gWtlo[3L * 1048576];

// ---------------- helpers ----------------
__device__ __forceinline__ uint32_t smem_u32(const void* p) {
    uint32_t a;
    asm("{ .reg .u64 t; cvta.to.shared.u64 t, %1; cvt.u32.u64 %0, t; }" : "=r"(a) : "l"(p));
    return a;
}
// Swizzle<2,4,3> on 64B rows: XOR 16B-chunk index bits with row bits (256B period)
__device__ __forceinline__ uint32_t SZ(uint32_t a) { return a ^ (((a >> 7) & 3u) << 4); }

__device__ __forceinline__ void cp16(uint32_t dst, const void* src) {
    asm volatile("cp.async.cg.shared.global [%0], [%1], 16;\n" :: "r"(dst), "l"(src));
}
__device__ __forceinline__ void cp_commit() { asm volatile("cp.async.commit_group;\n"); }
template<int N> __device__ __forceinline__ void cp_wait() {
    asm volatile("cp.async.wait_group %0;\n" :: "n"(N));
}
__device__ __forceinline__ void ldm4(uint32_t* r, uint32_t addr) {
    asm volatile("ldmatrix.sync.aligned.m8n8.x4.shared.b16 {%0,%1,%2,%3}, [%4];"
                 : "=r"(r[0]), "=r"(r[1]), "=r"(r[2]), "=r"(r[3]) : "r"(addr));
}
__device__ __forceinline__ void mma16816(float* d, const uint32_t* a, const uint32_t* b) {
    asm volatile(
        "mma.sync.aligned.m16n8k16.row.col.f32.bf16.bf16.f32 "
        "{%0,%1,%2,%3}, {%4,%5,%6,%7}, {%8,%9}, {%0,%1,%2,%3};"
        : "+f"(d[0]), "+f"(d[1]), "+f"(d[2]), "+f"(d[3])
        : "r"(a[0]), "r"(a[1]), "r"(a[2]), "r"(a[3]), "r"(b[0]), "r"(b[1]));
}

// ---------------- conversion prepasses ----------------
__global__ __launch_bounds__(256)
void convert_A_kernel(const float* __restrict__ q, const float* __restrict__ k,
                      const float* __restrict__ v)
{
    const int which = blockIdx.y;
    const float* src = (which == 0) ? q : (which == 1) ? k : v;
    __nv_bfloat16* hi = gAhi + (size_t)which * 33554432;
    __nv_bfloat16* lo = gAlo + (size_t)which * 33554432;

    size_t i4 = (size_t)blockIdx.x * blockDim.x + threadIdx.x;   // 0..8388607
    float4 x = reinterpret_cast<const float4*>(src)[i4];

    __nv_bfloat162 h01 = __floats2bfloat162_rn(x.x, x.y);
    __nv_bfloat162 h23 = __floats2bfloat162_rn(x.z, x.w);
    __nv_bfloat162 l01 = __floats2bfloat162_rn(x.x - __bfloat162float(h01.x),
                                               x.y - __bfloat162float(h01.y));
    __nv_bfloat162 l23 = __floats2bfloat162_rn(x.z - __bfloat162float(h23.x),
                                               x.w - __bfloat162float(h23.y));
    uint2 uh, ul;
    uh.x = *reinterpret_cast<unsigned*>(&h01); uh.y = *reinterpret_cast<unsigned*>(&h23);
    ul.x = *reinterpret_cast<unsigned*>(&l01); ul.y = *reinterpret_cast<unsigned*>(&l23);
    reinterpret_cast<uint2*>(hi)[i4] = uh;
    reinterpret_cast<uint2*>(lo)[i4] = ul;
}

__global__ __launch_bounds__(256)
void convert_W_kernel(const float* __restrict__ wq, const float* __restrict__ wk,
                      const float* __restrict__ wv)
{
    const int which = blockIdx.z;
    const float* W = (which == 0) ? wq : (which == 1) ? wk : wv;
    __nv_bfloat16* hi = gWthi + (size_t)which * 1048576;
    __nv_bfloat16* lo = gWtlo + (size_t)which * 1048576;

    __shared__ float tile[32][33];
    const int bx = blockIdx.x * 32;   // n block
    const int by = blockIdx.y * 32;   // k block
    const int tx = threadIdx.x & 31;
    const int ty = threadIdx.x >> 5;  // 0..7

#pragma unroll
    for (int i = 0; i < 32; i += 8)
        tile[ty + i][tx] = W[(size_t)(by + ty + i) * 1024 + bx + tx];
    __syncthreads();
#pragma unroll
    for (int i = 0; i < 32; i += 8) {
        float x = tile[tx][ty + i];                 // = W[by+tx][bx+ty+i]
        __nv_bfloat16 h = __float2bfloat16_rn(x);
        __nv_bfloat16 l = __float2bfloat16_rn(x - __bfloat162float(h));
        size_t o = (size_t)(bx + ty + i) * 1024 + by + tx;   // Wt[n][k]
        hi[o] = h;
        lo[o] = l;
    }
}

// ---------------- HMMA GEMM: C[M,N] = A @ W  (3-term bf16 split) -------------
// Tile 128x256xK32, 8 warps (2m x 4n, 64x64 warp tiles), double-buffered cp.async.
// smem/stage: Ahi 8K | Alo 8K | Bhi 16K | Blo 16K = 48K; two stages = 96K.
static constexpr int STAGE = 49152;

__global__ __launch_bounds__(256, 1)
void gemm_mma_kernel()
{
    extern __shared__ char smem[];
    const int which = blockIdx.z;
    const int n0 = blockIdx.x * 256;
    const int m0 = blockIdx.y * 128;
    const int tid = threadIdx.x;
    const int wid = tid >> 5, lane = tid & 31;

    const uint32_t tiles = (smem_u32(smem) + 1023) & ~1023u;

    const __nv_bfloat16* Ah = gAhi + (size_t)which * 33554432;
    const __nv_bfloat16* Al = gAlo + (size_t)which * 33554432;
    const __nv_bfloat16* Bh = gWthi + (size_t)which * 1048576;
    const __nv_bfloat16* Bl = gWtlo + (size_t)which * 1048576;
    float* C = (which == 0) ? gQ : (which == 1) ? gK : gV;

    const int mbase_w = (wid & 1) * 64;
    const int nbase_w = (wid >> 1) * 64;

    float acc[4][8][4];
#pragma unroll
    for (int i = 0; i < 4; i++)
#pragma unroll
        for (int j = 0; j < 8; j++)
#pragma unroll
            for (int q = 0; q < 4; q++) acc[i][j][q] = 0.f;

    auto load_chunk = [&](int buf, int c) {
        const uint32_t base = tiles + buf * STAGE;
        const int k0 = c * 32;
#pragma unroll
        for (int i = tid; i < 512; i += 256) {          // A: 128 rows x 4 chunks
            int r = i >> 2, c4 = i & 3;
            size_t gb = ((size_t)(m0 + r) * 1024 + k0 + c4 * 8) * 2;
            uint32_t d = SZ((uint32_t)(r * 64 + c4 * 16));
            cp16(base + d, (const char*)Ah + gb);
            cp16(base + 8192 + d, (const char*)Al + gb);
        }
#pragma unroll
        for (int i = tid; i < 1024; i += 256) {         // B: 256 rows x 4 chunks
            int r = i >> 2, c4 = i & 3;
            size_t gb = ((size_t)(n0 + r) * 1024 + k0 + c4 * 8) * 2;
            uint32_t d = SZ((uint32_t)(r * 64 + c4 * 16));
            cp16(base + 16384 + d, (const char*)Bh + gb);
            cp16(base + 32768 + d, (const char*)Bl + gb);
        }
        cp_commit();
    };

    load_chunk(0, 0);

    // lane-invariant pieces of ldmatrix addressing
    const int arow = (lane & 7) + ((lane >> 3) & 1) * 8;   // A: phase0/2 rows m0-7, 1/3 m8-15
    const int aoff = ((lane >> 4) & 1) * 16;               //     phase2/3 second 16B (k8-15)
    const int brow = (lane & 7) + ((lane >> 4) & 1) * 8;   // B: phase0/1 n0-7, 2/3 n8-15
    const int boff = ((lane >> 3) & 1) * 16;               //     phase1/3 second 16B

    for (int c = 0; c < 32; ++c) {
        if (c + 1 < 32) { load_chunk((c + 1) & 1, c + 1); cp_wait<1>(); }
        else            { cp_wait<0>(); }
        __syncthreads();

        const uint32_t ab_hi = tiles + (c & 1) * STAGE;
        const uint32_t ab_lo = ab_hi + 8192;
        const uint32_t bb_hi = ab_hi + 16384;
        const uint32_t bb_lo = ab_hi + 32768;

#pragma unroll
        for (int s = 0; s < 2; ++s) {
            uint32_t ah[4][4], al[4][4], bb[8][2];
#pragma unroll
            for (int mf = 0; mf < 4; ++mf) {
                uint32_t u = SZ((uint32_t)((mbase_w + mf * 16 + arow) * 64 + s * 32 + aoff));
                ldm4(ah[mf], ab_hi + u);
                ldm4(al[mf], ab_lo + u);
            }
#pragma unroll
            for (int bg = 0; bg < 4; ++bg) {
                uint32_t u = SZ((uint32_t)((nbase_w + bg * 16 + brow) * 64 + s * 32 + boff));
                uint32_t r[4];
                ldm4(r, bb_hi + u);
                bb[2 * bg][0] = r[0]; bb[2 * bg][1] = r[1];
                bb[2 * bg + 1][0] = r[2]; bb[2 * bg + 1][1] = r[3];
            }
#pragma unroll
            for (int mf = 0; mf < 4; ++mf)
#pragma unroll
                for (int nf = 0; nf < 8; ++nf) {
                    mma16816(acc[mf][nf], ah[mf], bb[nf]);   // hi*hi
                    mma16816(acc[mf][nf], al[mf], bb[nf]);   // lo*hi
                }
#pragma unroll
            for (int bg = 0; bg < 4; ++bg) {
                uint32_t u = SZ((uint32_t)((nbase_w + bg * 16 + brow) * 64 + s * 32 + boff));
                uint32_t r[4];
                ldm4(r, bb_lo + u);
                bb[2 * bg][0] = r[0]; bb[2 * bg][1] = r[1];
                bb[2 * bg + 1][0] = r[2]; bb[2 * bg + 1][1] = r[3];
            }
#pragma unroll
            for (int mf = 0; mf < 4; ++mf)
#pragma unroll
                for (int nf = 0; nf < 8; ++nf)
                    mma16816(acc[mf][nf], ah[mf], bb[nf]);   // hi*lo
        }
        __syncthreads();
    }

    // epilogue: fp32 accumulators -> C
    const int lrow = lane >> 2;
    const int lcol = (lane & 3) * 2;
#pragma unroll
    for (int mf = 0; mf < 4; ++mf) {
#pragma unroll
        for (int nf = 0; nf < 8; ++nf) {
            int rm = m0 + mbase_w + mf * 16 + lrow;
            int cn = n0 + nbase_w + nf * 8 + lcol;
            float2 v0 = make_float2(acc[mf][nf][0], acc[mf][nf][1]);
            float2 v1 = make_float2(acc[mf][nf][2], acc[mf][nf][3]);
            *reinterpret_cast<float2*>(C + (size_t)rm * 1024 + cn) = v0;
            *reinterpret_cast<float2*>(C + (size_t)(rm + 8) * 1024 + cn) = v1;
        }
    }
}

// ---------------- p_attn partials: LN(K)^T LN(V) over an n-chunk -------------
__global__ __launch_bounds__(256)
void pattn_partial_kernel(const float* __restrict__ lnk_s, const float* __restrict__ lnk_b,
                          const float* __restrict__ lnv_s, const float* __restrict__ lnv_b)
{
    const int bh = blockIdx.x;
    const int chunk = blockIdx.y;
    const int b = bh >> 4, h = bh & 15;
    const int n0 = chunk * ROWS_PER_CHUNK;
    const long base = (long)b * (Ss * Ff) + (long)h * (512 * 1024);

    __shared__ float ks[16][64];
    __shared__ float vs[16][64];
    __shared__ float sks[64], skb[64], svs[64], svb[64];

    const int t = threadIdx.x;
    const int warp = t >> 5, lane = t & 31;

    if (t < 64) {
        sks[t] = lnk_s[h * 64 + t];
        skb[t] = lnk_b[h * 64 + t];
        svs[t] = lnv_s[h * 64 + t];
        svb[t] = lnv_b[h * 64 + t];
    }

    float acc[4][4];
#pragma unroll
    for (int i = 0; i < 4; i++)
#pragma unroll
        for (int j = 0; j < 4; j++) acc[i][j] = 0.f;

    const int td = (t >> 4) * 4;
    const int te = (t & 15) * 4;

    for (int r0 = 0; r0 < ROWS_PER_CHUNK; r0 += 16) {
        __syncthreads();
#pragma unroll
        for (int rr = 0; rr < 2; rr++) {
            int r = 2 * warp + rr;
            long off = base + (long)(n0 + r0 + r) * 64;

            float kx0 = gK[off + lane];
            float kx1 = gK[off + 32 + lane];
            float vx0 = gV[off + lane];
            float vx1 = gV[off + 32 + lane];

            float ksum = kx0 + kx1, ksq = kx0 * kx0 + kx1 * kx1;
            float vsum = vx0 + vx1, vsq = vx0 * vx0 + vx1 * vx1;
#pragma unroll
            for (int o = 16; o > 0; o >>= 1) {
                ksum += __shfl_xor_sync(0xffffffffu, ksum, o);
                ksq  += __shfl_xor_sync(0xffffffffu, ksq, o);
                vsum += __shfl_xor_sync(0xffffffffu, vsum, o);
                vsq  += __shfl_xor_sync(0xffffffffu, vsq, o);
            }
            float kmu = ksum * (1.f / 64.f);
            float kvar = ksq * (1.f / 64.f) - kmu * kmu;
            float krs = rsqrtf(kvar + 1e-6f);
            float vmu = vsum * (1.f / 64.f);
            float vvar = vsq * (1.f / 64.f) - vmu * vmu;
            float vrs = rsqrtf(vvar + 1e-6f);

            ks[r][lane]      = (kx0 - kmu) * krs * sks[lane]      + skb[lane];
            ks[r][lane + 32] = (kx1 - kmu) * krs * sks[lane + 32] + skb[lane + 32];
            vs[r][lane]      = (vx0 - vmu) * vrs * svs[lane]      + svb[lane];
            vs[r][lane + 32] = (vx1 - vmu) * vrs * svs[lane + 32] + svb[lane + 32];
        }
        __syncthreads();

#pragma unroll
        for (int r = 0; r < 16; r++) {
            float4 kq = *(const float4*)(&ks[r][td]);
            float4 vq = *(const float4*)(&vs[r][te]);
            float ka[4] = {kq.x, kq.y, kq.z, kq.w};
            float va[4] = {vq.x, vq.y, vq.z, vq.w};
#pragma unroll
            for (int i = 0; i < 4; i++)
#pragma unroll
                for (int j = 0; j < 4; j++)
                    acc[i][j] += ka[i] * va[j];
        }
    }

    float* p = gPpart + ((long)chunk * 64 + bh) * 4096;
#pragma unroll
    for (int i = 0; i < 4; i++)
#pragma unroll
        for (int j = 0; j < 4; j++)
            p[(td + i) * 64 + (te + j)] = acc[i][j];
}

__global__ void pattn_reduce_kernel(float* __restrict__ pout)
{
    int i = blockIdx.x * blockDim.x + threadIdx.x;
    if (i >= 64 * 4096) return;
    int bh = i >> 12;
    int idx = i & 4095;
    float s = 0.f;
#pragma unroll
    for (int c = 0; c < NCHUNK; c++)
        s += gPpart[((long)c * 64 + bh) * 4096 + idx];
    pout[i] = s * (1.f / 8192.f);
}

__global__ __launch_bounds__(256)
void out_kernel(const float* __restrict__ pattn, float* __restrict__ out)
{
    const int bh = blockIdx.y;
    const int b = bh >> 4, h = bh & 15;
    const int n0 = blockIdx.x * 64;

    __shared__ float ps[64][64];
    __shared__ float qs[64][68];

    const int t = threadIdx.x;
    const float* P = pattn + (long)bh * 4096;
    for (int i = t; i < 4096; i += 256)
        ps[i >> 6][i & 63] = P[i];

    const long base = (long)b * (Ss * Ff) + (long)h * 524288 + (long)n0 * 64;
#pragma unroll
    for (int it = 0; it < 4; it++) {
        int i = t * 4 + it * 1024;
        *(float4*)(&qs[i >> 6][i & 63]) = *(const float4*)(gQ + base + i);
    }
    __syncthreads();

    const int r  = t >> 2;
    const int eg = (t & 3) * 16;

    float acc[16];
#pragma unroll
    for (int j = 0; j < 16; j++) acc[j] = 0.f;

#pragma unroll
    for (int d = 0; d < 64; d++) {
        float q = qs[r][d];
#pragma unroll
        for (int j4 = 0; j4 < 4; j4++) {
            float4 pv = *(const float4*)(&ps[d][eg + j4 * 4]);
            acc[j4 * 4 + 0] += q * pv.x;
            acc[j4 * 4 + 1] += q * pv.y;
            acc[j4 * 4 + 2] += q * pv.z;
            acc[j4 * 4 + 3] += q * pv.w;
        }
    }

    float* o = out + base + (long)r * 64 + eg;
#pragma unroll
    for (int j4 = 0; j4 < 4; j4++)
        *(float4*)(o + j4 * 4) = make_float4(acc[j4 * 4 + 0], acc[j4 * 4 + 1],
                                             acc[j4 * 4 + 2], acc[j4 * 4 + 3]);
}

// ---------------- launch ----------------------------------------------------
extern "C" void kernel_launch(void* const* d_in, const int* in_sizes, int n_in,
                              void* d_out, int out_size)
{
    (void)in_sizes; (void)n_in; (void)out_size;
    const float* query = (const float*)d_in[0];
    const float* key   = (const float*)d_in[1];
    const float* value = (const float*)d_in[2];
    const float* Wq    = (const float*)d_in[3];
    const float* Wk    = (const float*)d_in[4];
    const float* Wv    = (const float*)d_in[5];
    const float* lnk_s = (const float*)d_in[6];
    const float* lnk_b = (const float*)d_in[7];
    const float* lnv_s = (const float*)d_in[8];
    const float* lnv_b = (const float*)d_in[9];

    float* out = (float*)d_out;
    float* pout = out + QELEMS;

    cudaFuncSetAttribute(gemm_mma_kernel, cudaFuncAttributeMaxDynamicSharedMemorySize,
                         2 * STAGE + 1024);

    convert_A_kernel<<<dim3(32768, 3), 256>>>(query, key, value);
    convert_W_kernel<<<dim3(32, 32, 3), 256>>>(Wq, Wk, Wv);

    gemm_mma_kernel<<<dim3(4, 256, 3), 256, 2 * STAGE + 1024>>>();

    dim3 pgrid(64, NCHUNK);
    pattn_partial_kernel<<<pgrid, 256>>>(lnk_s, lnk_b, lnv_s, lnv_b);
    pattn_reduce_kernel<<<(64 * 4096 + 255) / 256, 256>>>(pout);

    dim3 ogrid(8192 / 64, 64);
    out_kernel<<<ogrid, 256>>>(pout, out);
}

// round 4
// speedup vs baseline: 2.1603x; 1.0084x over previous
#include <cuda_runtime.h>
#include <cuda_bf16.h>
#include <cstdint>

// ---------------- problem constants ----------------
static constexpr int Bb = 4, Ss = 8192, Ff = 1024, Hh = 16, Dd = 64;
static constexpr int Mm = Bb * Ss;              // 32768
static constexpr int Kk = 1024, Nn = 1024;
static constexpr long QELEMS = (long)Mm * Ff;   // 33554432
static constexpr int NCHUNK = 16;
static constexpr int ROWS_PER_CHUNK = 8192 / NCHUNK;  // 512

// ---------------- scratch (device globals) ----------------
__device__ float gQ[33554432];
__device__ float gK[33554432];
__device__ float gV[33554432];
__device__ float gPpart[(long)NCHUNK * 64 * 4096];
__device__ __nv_bfloat16 gAhi[3L * 33554432];
__device__ __nv_bfloat16 gAlo[3L * 33554432];
__device__ __nv_bfloat16 gWthi[3L * 1048576];   // W^T: [n][k], k contiguous
__device__ __nv_bfloat16 gWtlo[3L * 1048576];

// ---------------- helpers ----------------
__device__ __forceinline__ uint32_t smem_u32(const void* p) {
    uint32_t a;
    asm("{ .reg .u64 t; cvta.to.shared.u64 t, %1; cvt.u32.u64 %0, t; }" : "=r"(a) : "l"(p));
    return a;
}
// Swizzle<2,4,3> on 64B rows: XOR 16B-chunk index bits with row bits (256B period)
__device__ __forceinline__ uint32_t SZ(uint32_t a) { return a ^ (((a >> 7) & 3u) << 4); }

__device__ __forceinline__ void cp16(uint32_t dst, const void* src) {
    asm volatile("cp.async.cg.shared.global [%0], [%1], 16;\n" :: "r"(dst), "l"(src));
}
__device__ __forceinline__ void cp_commit() { asm volatile("cp.async.commit_group;\n"); }
template<int N> __device__ __forceinline__ void cp_wait() {
    asm volatile("cp.async.wait_group %0;\n" :: "n"(N));
}
__device__ __forceinline__ void ldm4(uint32_t* r, uint32_t addr) {
    asm volatile("ldmatrix.sync.aligned.m8n8.x4.shared.b16 {%0,%1,%2,%3}, [%4];"
                 : "=r"(r[0]), "=r"(r[1]), "=r"(r[2]), "=r"(r[3]) : "r"(addr));
}
__device__ __forceinline__ void mma16816(float* d, const uint32_t* a, const uint32_t* b) {
    asm volatile(
        "mma.sync.aligned.m16n8k16.row.col.f32.bf16.bf16.f32 "
        "{%0,%1,%2,%3}, {%4,%5,%6,%7}, {%8,%9}, {%0,%1,%2,%3};"
        : "+f"(d[0]), "+f"(d[1]), "+f"(d[2]), "+f"(d[3])
        : "r"(a[0]), "r"(a[1]), "r"(a[2]), "r"(a[3]), "r"(b[0]), "r"(b[1]));
}

// ---------------- conversion prepasses ----------------
__global__ __launch_bounds__(256)
void convert_A_kernel(const float* __restrict__ q, const float* __restrict__ k,
                      const float* __restrict__ v)
{
    const int which = blockIdx.y;
    const float* src = (which == 0) ? q : (which == 1) ? k : v;
    __nv_bfloat16* hi = gAhi + (size_t)which * 33554432;
    __nv_bfloat16* lo = gAlo + (size_t)which * 33554432;

    size_t i4 = (size_t)blockIdx.x * blockDim.x + threadIdx.x;   // 0..8388607
    float4 x = reinterpret_cast<const float4*>(src)[i4];

    __nv_bfloat162 h01 = __floats2bfloat162_rn(x.x, x.y);
    __nv_bfloat162 h23 = __floats2bfloat162_rn(x.z, x.w);
    __nv_bfloat162 l01 = __floats2bfloat162_rn(x.x - __bfloat162float(h01.x),
                                               x.y - __bfloat162float(h01.y));
    __nv_bfloat162 l23 = __floats2bfloat162_rn(x.z - __bfloat162float(h23.x),
                                               x.w - __bfloat162float(h23.y));
    uint2 uh, ul;
    uh.x = *reinterpret_cast<unsigned*>(&h01); uh.y = *reinterpret_cast<unsigned*>(&h23);
    ul.x = *reinterpret_cast<unsigned*>(&l01); ul.y = *reinterpret_cast<unsigned*>(&l23);
    reinterpret_cast<uint2*>(hi)[i4] = uh;
    reinterpret_cast<uint2*>(lo)[i4] = ul;
}

__global__ __launch_bounds__(256)
void convert_W_kernel(const float* __restrict__ wq, const float* __restrict__ wk,
                      const float* __restrict__ wv)
{
    const int which = blockIdx.z;
    const float* W = (which == 0) ? wq : (which == 1) ? wk : wv;
    __nv_bfloat16* hi = gWthi + (size_t)which * 1048576;
    __nv_bfloat16* lo = gWtlo + (size_t)which * 1048576;

    __shared__ float tile[32][33];
    const int bx = blockIdx.x * 32;   // n block
    const int by = blockIdx.y * 32;   // k block
    const int tx = threadIdx.x & 31;
    const int ty = threadIdx.x >> 5;  // 0..7

#pragma unroll
    for (int i = 0; i < 32; i += 8)
        tile[ty + i][tx] = W[(size_t)(by + ty + i) * 1024 + bx + tx];
    __syncthreads();
#pragma unroll
    for (int i = 0; i < 32; i += 8) {
        float x = tile[tx][ty + i];                 // = W[by+tx][bx+ty+i]
        __nv_bfloat16 h = __float2bfloat16_rn(x);
        __nv_bfloat16 l = __float2bfloat16_rn(x - __bfloat162float(h));
        size_t o = (size_t)(bx + ty + i) * 1024 + by + tx;   // Wt[n][k]
        hi[o] = h;
        lo[o] = l;
    }
}

// ---------------- HMMA GEMM: C[M,N] = A @ W  (3-term bf16 split) -------------
// Tile 128x256xK32, 8 warps (2m x 4n, 64x64 warp tiles), double-buffered cp.async.
// smem/stage: Ahi 8K | Alo 8K | Bhi 16K | Blo 16K = 48K; two stages = 96K.
static constexpr int STAGE = 49152;

__global__ __launch_bounds__(256, 1)
void gemm_mma_kernel()
{
    extern __shared__ char smem[];
    const int which = blockIdx.z;
    const int n0 = blockIdx.x * 256;
    const int m0 = blockIdx.y * 128;
    const int tid = threadIdx.x;
    const int wid = tid >> 5, lane = tid & 31;

    const uint32_t tiles = (smem_u32(smem) + 1023) & ~1023u;

    const __nv_bfloat16* Ah = gAhi + (size_t)which * 33554432;
    const __nv_bfloat16* Al = gAlo + (size_t)which * 33554432;
    const __nv_bfloat16* Bh = gWthi + (size_t)which * 1048576;
    const __nv_bfloat16* Bl = gWtlo + (size_t)which * 1048576;
    float* C = (which == 0) ? gQ : (which == 1) ? gK : gV;

    const int mbase_w = (wid & 1) * 64;
    const int nbase_w = (wid >> 1) * 64;

    float acc[4][8][4];
#pragma unroll
    for (int i = 0; i < 4; i++)
#pragma unroll
        for (int j = 0; j < 8; j++)
#pragma unroll
            for (int q = 0; q < 4; q++) acc[i][j][q] = 0.f;

    auto load_chunk = [&](int buf, int c) {
        const uint32_t base = tiles + buf * STAGE;
        const int k0 = c * 32;
#pragma unroll
        for (int i = tid; i < 512; i += 256) {          // A: 128 rows x 4 chunks
            int r = i >> 2, c4 = i & 3;
            size_t gb = ((size_t)(m0 + r) * 1024 + k0 + c4 * 8) * 2;
            uint32_t d = SZ((uint32_t)(r * 64 + c4 * 16));
            cp16(base + d, (const char*)Ah + gb);
            cp16(base + 8192 + d, (const char*)Al + gb);
        }
#pragma unroll
        for (int i = tid; i < 1024; i += 256) {         // B: 256 rows x 4 chunks
            int r = i >> 2, c4 = i & 3;
            size_t gb = ((size_t)(n0 + r) * 1024 + k0 + c4 * 8) * 2;
            uint32_t d = SZ((uint32_t)(r * 64 + c4 * 16));
            cp16(base + 16384 + d, (const char*)Bh + gb);
            cp16(base + 32768 + d, (const char*)Bl + gb);
        }
        cp_commit();
    };

    load_chunk(0, 0);

    // lane-invariant pieces of ldmatrix addressing
    const int arow = (lane & 7) + ((lane >> 3) & 1) * 8;
    const int aoff = ((lane >> 4) & 1) * 16;
    const int brow = (lane & 7) + ((lane >> 4) & 1) * 8;
    const int boff = ((lane >> 3) & 1) * 16;

    for (int c = 0; c < 32; ++c) {
        cp_wait<0>();              // this chunk's data landed
        __syncthreads();           // visible to all; prior compute done everywhere
        if (c + 1 < 32) load_chunk((c + 1) & 1, c + 1);   // overlaps compute below

        const uint32_t ab_hi = tiles + (c & 1) * STAGE;
        const uint32_t ab_lo = ab_hi + 8192;
        const uint32_t bb_hi = ab_hi + 16384;
        const uint32_t bb_lo = ab_hi + 32768;

#pragma unroll
        for (int s = 0; s < 2; ++s) {
            uint32_t ah[4][4], al[4][4], bh2[8][2], bl2[8][2];
            // all 16 LDSM issued up front; no register reuse between hi/lo B
#pragma unroll
            for (int bg = 0; bg < 4; ++bg) {
                uint32_t u = SZ((uint32_t)((nbase_w + bg * 16 + brow) * 64 + s * 32 + boff));
                uint32_t r[4];
                ldm4(r, bb_hi + u);
                bh2[2 * bg][0] = r[0]; bh2[2 * bg][1] = r[1];
                bh2[2 * bg + 1][0] = r[2]; bh2[2 * bg + 1][1] = r[3];
            }
#pragma unroll
            for (int mf = 0; mf < 4; ++mf) {
                uint32_t u = SZ((uint32_t)((mbase_w + mf * 16 + arow) * 64 + s * 32 + aoff));
                ldm4(ah[mf], ab_hi + u);
            }
#pragma unroll
            for (int mf = 0; mf < 4; ++mf) {
                uint32_t u = SZ((uint32_t)((mbase_w + mf * 16 + arow) * 64 + s * 32 + aoff));
                ldm4(al[mf], ab_lo + u);
            }
#pragma unroll
            for (int bg = 0; bg < 4; ++bg) {
                uint32_t u = SZ((uint32_t)((nbase_w + bg * 16 + brow) * 64 + s * 32 + boff));
                uint32_t r[4];
                ldm4(r, bb_lo + u);
                bl2[2 * bg][0] = r[0]; bl2[2 * bg][1] = r[1];
                bl2[2 * bg + 1][0] = r[2]; bl2[2 * bg + 1][1] = r[3];
            }
            // term-ordered MMAs: consecutive ops always hit distinct accumulators
#pragma unroll
            for (int mf = 0; mf < 4; ++mf)
#pragma unroll
                for (int nf = 0; nf < 8; ++nf)
                    mma16816(acc[mf][nf], ah[mf], bh2[nf]);   // hi*hi
#pragma unroll
            for (int mf = 0; mf < 4; ++mf)
#pragma unroll
                for (int nf = 0; nf < 8; ++nf)
                    mma16816(acc[mf][nf], al[mf], bh2[nf]);   // lo*hi
#pragma unroll
            for (int mf = 0; mf < 4; ++mf)
#pragma unroll
                for (int nf = 0; nf < 8; ++nf)
                    mma16816(acc[mf][nf], ah[mf], bl2[nf]);   // hi*lo
        }
    }

    // epilogue: fp32 accumulators -> C
    const int lrow = lane >> 2;
    const int lcol = (lane & 3) * 2;
#pragma unroll
    for (int mf = 0; mf < 4; ++mf) {
#pragma unroll
        for (int nf = 0; nf < 8; ++nf) {
            int rm = m0 + mbase_w + mf * 16 + lrow;
            int cn = n0 + nbase_w + nf * 8 + lcol;
            float2 v0 = make_float2(acc[mf][nf][0], acc[mf][nf][1]);
            float2 v1 = make_float2(acc[mf][nf][2], acc[mf][nf][3]);
            *reinterpret_cast<float2*>(C + (size_t)rm * 1024 + cn) = v0;
            *reinterpret_cast<float2*>(C + (size_t)(rm + 8) * 1024 + cn) = v1;
        }
    }
}

// ---------------- p_attn partials: LN(K)^T LN(V) over an n-chunk -------------
__global__ __launch_bounds__(256)
void pattn_partial_kernel(const float* __restrict__ lnk_s, const float* __restrict__ lnk_b,
                          const float* __restrict__ lnv_s, const float* __restrict__ lnv_b)
{
    const int bh = blockIdx.x;
    const int chunk = blockIdx.y;
    const int b = bh >> 4, h = bh & 15;
    const int n0 = chunk * ROWS_PER_CHUNK;
    const long base = (long)b * (Ss * Ff) + (long)h * (512 * 1024);

    __shared__ float ks[16][64];
    __shared__ float vs[16][64];
    __shared__ float sks[64], skb[64], svs[64], svb[64];

    const int t = threadIdx.x;
    const int warp = t >> 5, lane = t & 31;

    if (t < 64) {
        sks[t] = lnk_s[h * 64 + t];
        skb[t] = lnk_b[h * 64 + t];
        svs[t] = lnv_s[h * 64 + t];
        svb[t] = lnv_b[h * 64 + t];
    }

    float acc[4][4];
#pragma unroll
    for (int i = 0; i < 4; i++)
#pragma unroll
        for (int j = 0; j < 4; j++) acc[i][j] = 0.f;

    const int td = (t >> 4) * 4;
    const int te = (t & 15) * 4;

    for (int r0 = 0; r0 < ROWS_PER_CHUNK; r0 += 16) {
        __syncthreads();
#pragma unroll
        for (int rr = 0; rr < 2; rr++) {
            int r = 2 * warp + rr;
            long off = base + (long)(n0 + r0 + r) * 64;

            float kx0 = gK[off + lane];
            float kx1 = gK[off + 32 + lane];
            float vx0 = gV[off + lane];
            float vx1 = gV[off + 32 + lane];

            float ksum = kx0 + kx1, ksq = kx0 * kx0 + kx1 * kx1;
            float vsum = vx0 + vx1, vsq = vx0 * vx0 + vx1 * vx1;
#pragma unroll
            for (int o = 16; o > 0; o >>= 1) {
                ksum += __shfl_xor_sync(0xffffffffu, ksum, o);
                ksq  += __shfl_xor_sync(0xffffffffu, ksq, o);
                vsum += __shfl_xor_sync(0xffffffffu, vsum, o);
                vsq  += __shfl_xor_sync(0xffffffffu, vsq, o);
            }
            float kmu = ksum * (1.f / 64.f);
            float kvar = ksq * (1.f / 64.f) - kmu * kmu;
            float krs = rsqrtf(kvar + 1e-6f);
            float vmu = vsum * (1.f / 64.f);
            float vvar = vsq * (1.f / 64.f) - vmu * vmu;
            float vrs = rsqrtf(vvar + 1e-6f);

            ks[r][lane]      = (kx0 - kmu) * krs * sks[lane]      + skb[lane];
            ks[r][lane + 32] = (kx1 - kmu) * krs * sks[lane + 32] + skb[lane + 32];
            vs[r][lane]      = (vx0 - vmu) * vrs * svs[lane]      + svb[lane];
            vs[r][lane + 32] = (vx1 - vmu) * vrs * svs[lane + 32] + svb[lane + 32];
        }
        __syncthreads();

#pragma unroll
        for (int r = 0; r < 16; r++) {
            float4 kq = *(const float4*)(&ks[r][td]);
            float4 vq = *(const float4*)(&vs[r][te]);
            float ka[4] = {kq.x, kq.y, kq.z, kq.w};
            float va[4] = {vq.x, vq.y, vq.z, vq.w};
#pragma unroll
            for (int i = 0; i < 4; i++)
#pragma unroll
                for (int j = 0; j < 4; j++)
                    acc[i][j] += ka[i] * va[j];
        }
    }

    float* p = gPpart + ((long)chunk * 64 + bh) * 4096;
#pragma unroll
    for (int i = 0; i < 4; i++)
#pragma unroll
        for (int j = 0; j < 4; j++)
            p[(td + i) * 64 + (te + j)] = acc[i][j];
}

__global__ void pattn_reduce_kernel(float* __restrict__ pout)
{
    int i = blockIdx.x * blockDim.x + threadIdx.x;
    if (i >= 64 * 4096) return;
    int bh = i >> 12;
    int idx = i & 4095;
    float s = 0.f;
#pragma unroll
    for (int c = 0; c < NCHUNK; c++)
        s += gPpart[((long)c * 64 + bh) * 4096 + idx];
    pout[i] = s * (1.f / 8192.f);
}

__global__ __launch_bounds__(256)
void out_kernel(const float* __restrict__ pattn, float* __restrict__ out)
{
    const int bh = blockIdx.y;
    const int b = bh >> 4, h = bh & 15;
    const int n0 = blockIdx.x * 64;

    __shared__ float ps[64][64];
    __shared__ float qs[64][68];

    const int t = threadIdx.x;
    const float* P = pattn + (long)bh * 4096;
    for (int i = t; i < 4096; i += 256)
        ps[i >> 6][i & 63] = P[i];

    const long base = (long)b * (Ss * Ff) + (long)h * 524288 + (long)n0 * 64;
#pragma unroll
    for (int it = 0; it < 4; it++) {
        int i = t * 4 + it * 1024;
        *(float4*)(&qs[i >> 6][i & 63]) = *(const float4*)(gQ + base + i);
    }
    __syncthreads();

    const int r  = t >> 2;
    const int eg = (t & 3) * 16;

    float acc[16];
#pragma unroll
    for (int j = 0; j < 16; j++) acc[j] = 0.f;

#pragma unroll
    for (int d = 0; d < 64; d++) {
        float q = qs[r][d];
#pragma unroll
        for (int j4 = 0; j4 < 4; j4++) {
            float4 pv = *(const float4*)(&ps[d][eg + j4 * 4]);
            acc[j4 * 4 + 0] += q * pv.x;
            acc[j4 * 4 + 1] += q * pv.y;
            acc[j4 * 4 + 2] += q * pv.z;
            acc[j4 * 4 + 3] += q * pv.w;
        }
    }

    float* o = out + base + (long)r * 64 + eg;
#pragma unroll
    for (int j4 = 0; j4 < 4; j4++)
        *(float4*)(o + j4 * 4) = make_float4(acc[j4 * 4 + 0], acc[j4 * 4 + 1],
                                             acc[j4 * 4 + 2], acc[j4 * 4 + 3]);
}

// ---------------- launch ----------------------------------------------------
extern "C" void kernel_launch(void* const* d_in, const int* in_sizes, int n_in,
                              void* d_out, int out_size)
{
    (void)in_sizes; (void)n_in; (void)out_size;
    const float* query = (const float*)d_in[0];
    const float* key   = (const float*)d_in[1];
    const float* value = (const float*)d_in[2];
    const float* Wq    = (const float*)d_in[3];
    const float* Wk    = (const float*)d_in[4];
    const float* Wv    = (const float*)d_in[5];
    const float* lnk_s = (const float*)d_in[6];
    const float* lnk_b = (const float*)d_in[7];
    const float* lnv_s = (const float*)d_in[8];
    const float* lnv_b = (const float*)d_in[9];

    float* out = (float*)d_out;
    float* pout = out + QELEMS;

    cudaFuncSetAttribute(gemm_mma_kernel, cudaFuncAttributeMaxDynamicSharedMemorySize,
                         2 * STAGE + 1024);

    convert_A_kernel<<<dim3(32768, 3), 256>>>(query, key, value);
    convert_W_kernel<<<dim3(32, 32, 3), 256>>>(Wq, Wk, Wv);

    gemm_mma_kernel<<<dim3(4, 256, 3), 256, 2 * STAGE + 1024>>>();

    dim3 pgrid(64, NCHUNK);
    pattn_partial_kernel<<<pgrid, 256>>>(lnk_s, lnk_b, lnv_s, lnv_b);
    pattn_reduce_kernel<<<(64 * 4096 + 255) / 256, 256>>>(pout);

    dim3 ogrid(8192 / 64, 64);
    out_kernel<<<ogrid, 256>>>(pout, out);
}

// round 5
// speedup vs baseline: 2.6796x; 1.2404x over previous
#include <cuda_runtime.h>
#include <cuda_fp16.h>
#include <cstdint>

// ---------------- problem constants ----------------
static constexpr int Bb = 4, Ss = 8192, Ff = 1024, Hh = 16, Dd = 64;
static constexpr int Mm = Bb * Ss;              // 32768
static constexpr int Kk = 1024, Nn = 1024;
static constexpr long QELEMS = (long)Mm * Ff;   // 33554432
static constexpr int NCHUNK = 32;
static constexpr int ROWS_PER_CHUNK = 8192 / NCHUNK;  // 256

// ---------------- scratch (device globals) ----------------
__device__ float gQ[33554432];
__device__ float gK[33554432];
__device__ float gV[33554432];
__device__ float gPpart[(long)NCHUNK * 64 * 4096];
__device__ __half gAhi[3L * 33554432];
__device__ __half gAlo[3L * 33554432];
__device__ __half gWt[3L * 1048576];            // W^T: [n][k], k contiguous, fp16
 
// ---------------- helpers ----------------
__device__ __forceinline__ uint32_t smem_u32(const void* p) {
    uint32_t a;
    asm("{ .reg .u64 t; cvta.to.shared.u64 t, %1; cvt.u32.u64 %0, t; }" : "=r"(a) : "l"(p));
    return a;
}
// Swizzle<2,4,3> on 64B rows: XOR 16B-chunk index bits with row bits (256B period)
__device__ __forceinline__ uint32_t SZ(uint32_t a) { return a ^ (((a >> 7) & 3u) << 4); }

__device__ __forceinline__ void cp16(uint32_t dst, const void* src) {
    asm volatile("cp.async.cg.shared.global [%0], [%1], 16;\n" :: "r"(dst), "l"(src));
}
__device__ __forceinline__ void cp_commit() { asm volatile("cp.async.commit_group;\n"); }
template<int N> __device__ __forceinline__ void cp_wait() {
    asm volatile("cp.async.wait_group %0;\n" :: "n"(N));
}
__device__ __forceinline__ void ldm4(uint32_t* r, uint32_t addr) {
    asm volatile("ldmatrix.sync.aligned.m8n8.x4.shared.b16 {%0,%1,%2,%3}, [%4];"
                 : "=r"(r[0]), "=r"(r[1]), "=r"(r[2]), "=r"(r[3]) : "r"(addr));
}
__device__ __forceinline__ void mma16816(float* d, const uint32_t* a, const uint32_t* b) {
    asm volatile(
        "mma.sync.aligned.m16n8k16.row.col.f32.f16.f16.f32 "
        "{%0,%1,%2,%3}, {%4,%5,%6,%7}, {%8,%9}, {%0,%1,%2,%3};"
        : "+f"(d[0]), "+f"(d[1]), "+f"(d[2]), "+f"(d[3])
        : "r"(a[0]), "r"(a[1]), "r"(a[2]), "r"(a[3]), "r"(b[0]), "r"(b[1]));
}

// ---------------- conversion prepasses ----------------
__global__ __launch_bounds__(256)
void convert_A_kernel(const float* __restrict__ q, const float* __restrict__ k,
                      const float* __restrict__ v)
{
    const int which = blockIdx.y;
    const float* src = (which == 0) ? q : (which == 1) ? k : v;
    __half* hi = gAhi + (size_t)which * 33554432;
    __half* lo = gAlo + (size_t)which * 33554432;

    size_t i4 = (size_t)blockIdx.x * blockDim.x + threadIdx.x;   // 0..8388607
    float4 x = reinterpret_cast<const float4*>(src)[i4];

    __half h0 = __float2half_rn(x.x), h1 = __float2half_rn(x.y);
    __half h2 = __float2half_rn(x.z), h3 = __float2half_rn(x.w);
    __half l0 = __float2half_rn(x.x - __half2float(h0));
    __half l1 = __float2half_rn(x.y - __half2float(h1));
    __half l2 = __float2half_rn(x.z - __half2float(h2));
    __half l3 = __float2half_rn(x.w - __half2float(h3));

    __half2 uh0 = __halves2half2(h0, h1), uh1 = __halves2half2(h2, h3);
    __half2 ul0 = __halves2half2(l0, l1), ul1 = __halves2half2(l2, l3);
    uint2 uh, ul;
    uh.x = *reinterpret_cast<unsigned*>(&uh0); uh.y = *reinterpret_cast<unsigned*>(&uh1);
    ul.x = *reinterpret_cast<unsigned*>(&ul0); ul.y = *reinterpret_cast<unsigned*>(&ul1);
    reinterpret_cast<uint2*>(hi)[i4] = uh;
    reinterpret_cast<uint2*>(lo)[i4] = ul;
}

__global__ __launch_bounds__(256)
void convert_W_kernel(const float* __restrict__ wq, const float* __restrict__ wk,
                      const float* __restrict__ wv)
{
    const int which = blockIdx.z;
    const float* W = (which == 0) ? wq : (which == 1) ? wk : wv;
    __half* hi = gWt + (size_t)which * 1048576;

    __shared__ float tile[32][33];
    const int bx = blockIdx.x * 32;   // n block
    const int by = blockIdx.y * 32;   // k block
    const int tx = threadIdx.x & 31;
    const int ty = threadIdx.x >> 5;  // 0..7

#pragma unroll
    for (int i = 0; i < 32; i += 8)
        tile[ty + i][tx] = W[(size_t)(by + ty + i) * 1024 + bx + tx];
    __syncthreads();
#pragma unroll
    for (int i = 0; i < 32; i += 8) {
        float x = tile[tx][ty + i];                 // = W[by+tx][bx+ty+i]
        size_t o = (size_t)(bx + ty + i) * 1024 + by + tx;   // Wt[n][k]
        hi[o] = __float2half_rn(x);
    }
}

// ---------------- HMMA GEMM: C[M,N] = A @ W  (2-term fp16 split) -------------
// Tile 128x256xK32, 8 warps (2m x 4n, 64x64 warp tiles), double-buffered cp.async.
// smem/stage: Ahi 8K | Alo 8K | B 16K = 32K; two stages = 64K.
static constexpr int STAGE = 32768;

__global__ __launch_bounds__(256, 1)
void gemm_mma_kernel()
{
    extern __shared__ char smem[];
    const int which = blockIdx.z;
    const int n0 = blockIdx.x * 256;
    const int m0 = blockIdx.y * 128;
    const int tid = threadIdx.x;
    const int wid = tid >> 5, lane = tid & 31;

    const uint32_t tiles = (smem_u32(smem) + 1023) & ~1023u;

    const __half* Ah = gAhi + (size_t)which * 33554432;
    const __half* Al = gAlo + (size_t)which * 33554432;
    const __half* Bp = gWt + (size_t)which * 1048576;
    float* C = (which == 0) ? gQ : (which == 1) ? gK : gV;

    const int mbase_w = (wid & 1) * 64;
    const int nbase_w = (wid >> 1) * 64;

    float acc[4][8][4];
#pragma unroll
    for (int i = 0; i < 4; i++)
#pragma unroll
        for (int j = 0; j < 8; j++)
#pragma unroll
            for (int q = 0; q < 4; q++) acc[i][j][q] = 0.f;

    auto load_chunk = [&](int buf, int c) {
        const uint32_t base = tiles + buf * STAGE;
        const int k0 = c * 32;
#pragma unroll
        for (int i = tid; i < 512; i += 256) {          // A: 128 rows x 4 chunks
            int r = i >> 2, c4 = i & 3;
            size_t gb = ((size_t)(m0 + r) * 1024 + k0 + c4 * 8) * 2;
            uint32_t d = SZ((uint32_t)(r * 64 + c4 * 16));
            cp16(base + d, (const char*)Ah + gb);
            cp16(base + 8192 + d, (const char*)Al + gb);
        }
#pragma unroll
        for (int i = tid; i < 1024; i += 256) {         // B: 256 rows x 4 chunks
            int r = i >> 2, c4 = i & 3;
            size_t gb = ((size_t)(n0 + r) * 1024 + k0 + c4 * 8) * 2;
            uint32_t d = SZ((uint32_t)(r * 64 + c4 * 16));
            cp16(base + 16384 + d, (const char*)Bp + gb);
        }
        cp_commit();
    };

    load_chunk(0, 0);

    // lane-invariant pieces of ldmatrix addressing
    const int arow = (lane & 7) + ((lane >> 3) & 1) * 8;
    const int aoff = ((lane >> 4) & 1) * 16;
    const int brow = (lane & 7) + ((lane >> 4) & 1) * 8;
    const int boff = ((lane >> 3) & 1) * 16;

    for (int c = 0; c < 32; ++c) {
        cp_wait<0>();              // this chunk's data landed
        __syncthreads();           // visible to all; prior compute done everywhere
        if (c + 1 < 32) load_chunk((c + 1) & 1, c + 1);   // overlaps compute below

        const uint32_t ab_hi = tiles + (c & 1) * STAGE;
        const uint32_t ab_lo = ab_hi + 8192;
        const uint32_t bb    = ab_hi + 16384;

#pragma unroll
        for (int s = 0; s < 2; ++s) {
            uint32_t ah[4][4], al[4][4], bh2[8][2];
#pragma unroll
            for (int bg = 0; bg < 4; ++bg) {
                uint32_t u = SZ((uint32_t)((nbase_w + bg * 16 + brow) * 64 + s * 32 + boff));
                uint32_t r[4];
                ldm4(r, bb + u);
                bh2[2 * bg][0] = r[0]; bh2[2 * bg][1] = r[1];
                bh2[2 * bg + 1][0] = r[2]; bh2[2 * bg + 1][1] = r[3];
            }
#pragma unroll
            for (int mf = 0; mf < 4; ++mf) {
                uint32_t u = SZ((uint32_t)((mbase_w + mf * 16 + arow) * 64 + s * 32 + aoff));
                ldm4(ah[mf], ab_hi + u);
            }
#pragma unroll
            for (int mf = 0; mf < 4; ++mf) {
                uint32_t u = SZ((uint32_t)((mbase_w + mf * 16 + arow) * 64 + s * 32 + aoff));
                ldm4(al[mf], ab_lo + u);
            }
            // term-ordered MMAs: consecutive ops hit distinct accumulators
#pragma unroll
            for (int mf = 0; mf < 4; ++mf)
#pragma unroll
                for (int nf = 0; nf < 8; ++nf)
                    mma16816(acc[mf][nf], ah[mf], bh2[nf]);   // hi * B
#pragma unroll
            for (int mf = 0; mf < 4; ++mf)
#pragma unroll
                for (int nf = 0; nf < 8; ++nf)
                    mma16816(acc[mf][nf], al[mf], bh2[nf]);   // lo * B
        }
    }

    // epilogue: fp32 accumulators -> C
    const int lrow = lane >> 2;
    const int lcol = (lane & 3) * 2;
#pragma unroll
    for (int mf = 0; mf < 4; ++mf) {
#pragma unroll
        for (int nf = 0; nf < 8; ++nf) {
            int rm = m0 + mbase_w + mf * 16 + lrow;
            int cn = n0 + nbase_w + nf * 8 + lcol;
            float2 v0 = make_float2(acc[mf][nf][0], acc[mf][nf][1]);
            float2 v1 = make_float2(acc[mf][nf][2], acc[mf][nf][3]);
            *reinterpret_cast<float2*>(C + (size_t)rm * 1024 + cn) = v0;
            *reinterpret_cast<float2*>(C + (size_t)(rm + 8) * 1024 + cn) = v1;
        }
    }
}

// ---------------- p_attn partials: LN(K)^T LN(V) over an n-chunk -------------
__global__ __launch_bounds__(256)
void pattn_partial_kernel(const float* __restrict__ lnk_s, const float* __restrict__ lnk_b,
                          const float* __restrict__ lnv_s, const float* __restrict__ lnv_b)
{
    const int bh = blockIdx.x;
    const int chunk = blockIdx.y;
    const int b = bh >> 4, h = bh & 15;
    const int n0 = chunk * ROWS_PER_CHUNK;
    const long base = (long)b * (Ss * Ff) + (long)h * (512 * 1024);

    __shared__ float ks[16][64];
    __shared__ float vs[16][64];
    __shared__ float sks[64], skb[64], svs[64], svb[64];

    const int t = threadIdx.x;
    const int warp = t >> 5, lane = t & 31;

    if (t < 64) {
        sks[t] = lnk_s[h * 64 + t];
        skb[t] = lnk_b[h * 64 + t];
        svs[t] = lnv_s[h * 64 + t];
        svb[t] = lnv_b[h * 64 + t];
    }

    float acc[4][4];
#pragma unroll
    for (int i = 0; i < 4; i++)
#pragma unroll
        for (int j = 0; j < 4; j++) acc[i][j] = 0.f;

    const int td = (t >> 4) * 4;
    const int te = (t & 15) * 4;

    for (int r0 = 0; r0 < ROWS_PER_CHUNK; r0 += 16) {
        __syncthreads();
#pragma unroll
        for (int rr = 0; rr < 2; rr++) {
            int r = 2 * warp + rr;
            long off = base + (long)(n0 + r0 + r) * 64;

            float kx0 = gK[off + lane];
            float kx1 = gK[off + 32 + lane];
            float vx0 = gV[off + lane];
            float vx1 = gV[off + 32 + lane];

            float ksum = kx0 + kx1, ksq = kx0 * kx0 + kx1 * kx1;
            float vsum = vx0 + vx1, vsq = vx0 * vx0 + vx1 * vx1;
#pragma unroll
            for (int o = 16; o > 0; o >>= 1) {
                ksum += __shfl_xor_sync(0xffffffffu, ksum, o);
                ksq  += __shfl_xor_sync(0xffffffffu, ksq, o);
                vsum += __shfl_xor_sync(0xffffffffu, vsum, o);
                vsq  += __shfl_xor_sync(0xffffffffu, vsq, o);
            }
            float kmu = ksum * (1.f / 64.f);
            float kvar = ksq * (1.f / 64.f) - kmu * kmu;
            float krs = rsqrtf(kvar + 1e-6f);
            float vmu = vsum * (1.f / 64.f);
            float vvar = vsq * (1.f / 64.f) - vmu * vmu;
            float vrs = rsqrtf(vvar + 1e-6f);

            ks[r][lane]      = (kx0 - kmu) * krs * sks[lane]      + skb[lane];
            ks[r][lane + 32] = (kx1 - kmu) * krs * sks[lane + 32] + skb[lane + 32];
            vs[r][lane]      = (vx0 - vmu) * vrs * svs[lane]      + svb[lane];
            vs[r][lane + 32] = (vx1 - vmu) * vrs * svs[lane + 32] + svb[lane + 32];
        }
        __syncthreads();

#pragma unroll
        for (int r = 0; r < 16; r++) {
            float4 kq = *(const float4*)(&ks[r][td]);
            float4 vq = *(const float4*)(&vs[r][te]);
            float ka[4] = {kq.x, kq.y, kq.z, kq.w};
            float va[4] = {vq.x, vq.y, vq.z, vq.w};
#pragma unroll
            for (int i = 0; i < 4; i++)
#pragma unroll
                for (int j = 0; j < 4; j++)
                    acc[i][j] += ka[i] * va[j];
        }
    }

    float* p = gPpart + ((long)chunk * 64 + bh) * 4096;
#pragma unroll
    for (int i = 0; i < 4; i++)
#pragma unroll
        for (int j = 0; j < 4; j++)
            p[(td + i) * 64 + (te + j)] = acc[i][j];
}

__global__ void pattn_reduce_kernel(float* __restrict__ pout)
{
    int i = blockIdx.x * blockDim.x + threadIdx.x;
    if (i >= 64 * 4096) return;
    int bh = i >> 12;
    int idx = i & 4095;
    float s = 0.f;
#pragma unroll
    for (int c = 0; c < NCHUNK; c++)
        s += gPpart[((long)c * 64 + bh) * 4096 + idx];
    pout[i] = s * (1.f / 8192.f);
}

__global__ __launch_bounds__(256)
void out_kernel(const float* __restrict__ pattn, float* __restrict__ out)
{
    const int bh = blockIdx.y;
    const int b = bh >> 4, h = bh & 15;
    const int n0 = blockIdx.x * 64;

    __shared__ float ps[64][64];
    __shared__ float qs[64][68];

    const int t = threadIdx.x;
    const float* P = pattn + (long)bh * 4096;
    for (int i = t; i < 4096; i += 256)
        ps[i >> 6][i & 63] = P[i];

    const long base = (long)b * (Ss * Ff) + (long)h * 524288 + (long)n0 * 64;
#pragma unroll
    for (int it = 0; it < 4; it++) {
        int i = t * 4 + it * 1024;
        *(float4*)(&qs[i >> 6][i & 63]) = *(const float4*)(gQ + base + i);
    }
    __syncthreads();

    const int r  = t >> 2;
    const int eg = (t & 3) * 16;

    float acc[16];
#pragma unroll
    for (int j = 0; j < 16; j++) acc[j] = 0.f;

#pragma unroll
    for (int d = 0; d < 64; d++) {
        float q = qs[r][d];
#pragma unroll
        for (int j4 = 0; j4 < 4; j4++) {
            float4 pv = *(const float4*)(&ps[d][eg + j4 * 4]);
            acc[j4 * 4 + 0] += q * pv.x;
            acc[j4 * 4 + 1] += q * pv.y;
            acc[j4 * 4 + 2] += q * pv.z;
            acc[j4 * 4 + 3] += q * pv.w;
        }
    }

    float* o = out + base + (long)r * 64 + eg;
#pragma unroll
    for (int j4 = 0; j4 < 4; j4++)
        *(float4*)(o + j4 * 4) = make_float4(acc[j4 * 4 + 0], acc[j4 * 4 + 1],
                                             acc[j4 * 4 + 2], acc[j4 * 4 + 3]);
}

// ---------------- launch ----------------------------------------------------
extern "C" void kernel_launch(void* const* d_in, const int* in_sizes, int n_in,
                              void* d_out, int out_size)
{
    (void)in_sizes; (void)n_in; (void)out_size;
    const float* query = (const float*)d_in[0];
    const float* key   = (const float*)d_in[1];
    const float* value = (const float*)d_in[2];
    const float* Wq    = (const float*)d_in[3];
    const float* Wk    = (const float*)d_in[4];
    const float* Wv    = (const float*)d_in[5];
    const float* lnk_s = (const float*)d_in[6];
    const float* lnk_b = (const float*)d_in[7];
    const float* lnv_s = (const float*)d_in[8];
    const float* lnv_b = (const float*)d_in[9];

    float* out = (float*)d_out;
    float* pout = out + QELEMS;

    cudaFuncSetAttribute(gemm_mma_kernel, cudaFuncAttributeMaxDynamicSharedMemorySize,
                         2 * STAGE + 1024);

    convert_A_kernel<<<dim3(32768, 3), 256>>>(query, key, value);
    convert_W_kernel<<<dim3(32, 32, 3), 256>>>(Wq, Wk, Wv);

    gemm_mma_kernel<<<dim3(4, 256, 3), 256, 2 * STAGE + 1024>>>();

    dim3 pgrid(64, NCHUNK);
    pattn_partial_kernel<<<pgrid, 256>>>(lnk_s, lnk_b, lnv_s, lnv_b);
    pattn_reduce_kernel<<<(64 * 4096 + 255) / 256, 256>>>(pout);

    dim3 ogrid(8192 / 64, 64);
    out_kernel<<<ogrid, 256>>>(pout, out);
}

// round 6
// speedup vs baseline: 3.3144x; 1.2369x over previous
#include <cuda_runtime.h>
#include <cuda_fp16.h>
#include <cstdint>

// ---------------- problem constants ----------------
static constexpr int Bb = 4, Ss = 8192, Ff = 1024, Hh = 16, Dd = 64;
static constexpr int Mm = Bb * Ss;              // 32768
static constexpr int Kk = 1024, Nn = 1024;
static constexpr long QELEMS = (long)Mm * Ff;   // 33554432
static constexpr int NCHUNK = 32;
static constexpr int ROWS_PER_CHUNK = 8192 / NCHUNK;  // 256

// ---------------- scratch (device globals) ----------------
__device__ float gQ[33554432];
__device__ float gK[33554432];
__device__ float gV[33554432];
__device__ float gPpart[(long)NCHUNK * 64 * 4096];
__device__ __half gAh[3L * 33554432];
__device__ __half gWt[3L * 1048576];            // W^T: [n][k], k contiguous, fp16

// ---------------- helpers ----------------
__device__ __forceinline__ uint32_t smem_u32(const void* p) {
    uint32_t a;
    asm("{ .reg .u64 t; cvta.to.shared.u64 t, %1; cvt.u32.u64 %0, t; }" : "=r"(a) : "l"(p));
    return a;
}
// Swizzle<2,4,3> on 64B rows: XOR 16B-chunk index bits with row bits (256B period)
__device__ __forceinline__ uint32_t SZ(uint32_t a) { return a ^ (((a >> 7) & 3u) << 4); }

__device__ __forceinline__ void cp16(uint32_t dst, const void* src) {
    asm volatile("cp.async.cg.shared.global [%0], [%1], 16;\n" :: "r"(dst), "l"(src));
}
__device__ __forceinline__ void cp_commit() { asm volatile("cp.async.commit_group;\n"); }
template<int N> __device__ __forceinline__ void cp_wait() {
    asm volatile("cp.async.wait_group %0;\n" :: "n"(N));
}
__device__ __forceinline__ void ldm4(uint32_t* r, uint32_t addr) {
    asm volatile("ldmatrix.sync.aligned.m8n8.x4.shared.b16 {%0,%1,%2,%3}, [%4];"
                 : "=r"(r[0]), "=r"(r[1]), "=r"(r[2]), "=r"(r[3]) : "r"(addr));
}
__device__ __forceinline__ void mma16816(float* d, const uint32_t* a, const uint32_t* b) {
    asm volatile(
        "mma.sync.aligned.m16n8k16.row.col.f32.f16.f16.f32 "
        "{%0,%1,%2,%3}, {%4,%5,%6,%7}, {%8,%9}, {%0,%1,%2,%3};"
        : "+f"(d[0]), "+f"(d[1]), "+f"(d[2]), "+f"(d[3])
        : "r"(a[0]), "r"(a[1]), "r"(a[2]), "r"(a[3]), "r"(b[0]), "r"(b[1]));
}

// ---------------- conversion prepasses ----------------
__global__ __launch_bounds__(256)
void convert_A_kernel(const float* __restrict__ q, const float* __restrict__ k,
                      const float* __restrict__ v)
{
    const int which = blockIdx.y;
    const float* src = (which == 0) ? q : (which == 1) ? k : v;
    __half* hi = gAh + (size_t)which * 33554432;

    size_t i4 = (size_t)blockIdx.x * blockDim.x + threadIdx.x;   // 0..8388607
    float4 x = reinterpret_cast<const float4*>(src)[i4];

    __half2 uh0 = __halves2half2(__float2half_rn(x.x), __float2half_rn(x.y));
    __half2 uh1 = __halves2half2(__float2half_rn(x.z), __float2half_rn(x.w));
    uint2 uh;
    uh.x = *reinterpret_cast<unsigned*>(&uh0);
    uh.y = *reinterpret_cast<unsigned*>(&uh1);
    reinterpret_cast<uint2*>(hi)[i4] = uh;
}

__global__ __launch_bounds__(256)
void convert_W_kernel(const float* __restrict__ wq, const float* __restrict__ wk,
                      const float* __restrict__ wv)
{
    const int which = blockIdx.z;
    const float* W = (which == 0) ? wq : (which == 1) ? wk : wv;
    __half* hi = gWt + (size_t)which * 1048576;

    __shared__ float tile[32][33];
    const int bx = blockIdx.x * 32;   // n block
    const int by = blockIdx.y * 32;   // k block
    const int tx = threadIdx.x & 31;
    const int ty = threadIdx.x >> 5;  // 0..7

#pragma unroll
    for (int i = 0; i < 32; i += 8)
        tile[ty + i][tx] = W[(size_t)(by + ty + i) * 1024 + bx + tx];
    __syncthreads();
#pragma unroll
    for (int i = 0; i < 32; i += 8) {
        float x = tile[tx][ty + i];                 // = W[by+tx][bx+ty+i]
        size_t o = (size_t)(bx + ty + i) * 1024 + by + tx;   // Wt[n][k]
        hi[o] = __float2half_rn(x);
    }
}

// ---------------- HMMA GEMM: C[M,N] = A @ W  (1-term fp16) -------------------
// Tile 128x256xK32, 8 warps (2m x 4n, 64x64 warp tiles), double-buffered cp.async.
// smem/stage: A 8K | B 16K = 24K; two stages = 48K.
static constexpr int STAGE = 24576;

__global__ __launch_bounds__(256, 1)
void gemm_mma_kernel()
{
    extern __shared__ char smem[];
    const int which = blockIdx.z;
    const int n0 = blockIdx.x * 256;
    const int m0 = blockIdx.y * 128;
    const int tid = threadIdx.x;
    const int wid = tid >> 5, lane = tid & 31;

    const uint32_t tiles = (smem_u32(smem) + 1023) & ~1023u;

    const __half* Ah = gAh + (size_t)which * 33554432;
    const __half* Bp = gWt + (size_t)which * 1048576;
    float* C = (which == 0) ? gQ : (which == 1) ? gK : gV;

    const int mbase_w = (wid & 1) * 64;
    const int nbase_w = (wid >> 1) * 64;

    float acc[4][8][4];
#pragma unroll
    for (int i = 0; i < 4; i++)
#pragma unroll
        for (int j = 0; j < 8; j++)
#pragma unroll
            for (int q = 0; q < 4; q++) acc[i][j][q] = 0.f;

    auto load_chunk = [&](int buf, int c) {
        const uint32_t base = tiles + buf * STAGE;
        const int k0 = c * 32;
#pragma unroll
        for (int i = tid; i < 512; i += 256) {          // A: 128 rows x 4 chunks
            int r = i >> 2, c4 = i & 3;
            size_t gb = ((size_t)(m0 + r) * 1024 + k0 + c4 * 8) * 2;
            uint32_t d = SZ((uint32_t)(r * 64 + c4 * 16));
            cp16(base + d, (const char*)Ah + gb);
        }
#pragma unroll
        for (int i = tid; i < 1024; i += 256) {         // B: 256 rows x 4 chunks
            int r = i >> 2, c4 = i & 3;
            size_t gb = ((size_t)(n0 + r) * 1024 + k0 + c4 * 8) * 2;
            uint32_t d = SZ((uint32_t)(r * 64 + c4 * 16));
            cp16(base + 8192 + d, (const char*)Bp + gb);
        }
        cp_commit();
    };

    load_chunk(0, 0);

    // lane-invariant pieces of ldmatrix addressing
    const int arow = (lane & 7) + ((lane >> 3) & 1) * 8;
    const int aoff = ((lane >> 4) & 1) * 16;
    const int brow = (lane & 7) + ((lane >> 4) & 1) * 8;
    const int boff = ((lane >> 3) & 1) * 16;

    for (int c = 0; c < 32; ++c) {
        cp_wait<0>();              // this chunk's data landed
        __syncthreads();           // visible to all; prior compute done everywhere
        if (c + 1 < 32) load_chunk((c + 1) & 1, c + 1);   // overlaps compute below

        const uint32_t ab = tiles + (c & 1) * STAGE;
        const uint32_t bb = ab + 8192;

#pragma unroll
        for (int s = 0; s < 2; ++s) {
            uint32_t ah[4][4], bh2[8][2];
#pragma unroll
            for (int bg = 0; bg < 4; ++bg) {
                uint32_t u = SZ((uint32_t)((nbase_w + bg * 16 + brow) * 64 + s * 32 + boff));
                uint32_t r[4];
                ldm4(r, bb + u);
                bh2[2 * bg][0] = r[0]; bh2[2 * bg][1] = r[1];
                bh2[2 * bg + 1][0] = r[2]; bh2[2 * bg + 1][1] = r[3];
            }
#pragma unroll
            for (int mf = 0; mf < 4; ++mf) {
                uint32_t u = SZ((uint32_t)((mbase_w + mf * 16 + arow) * 64 + s * 32 + aoff));
                ldm4(ah[mf], ab + u);
            }
#pragma unroll
            for (int mf = 0; mf < 4; ++mf)
#pragma unroll
                for (int nf = 0; nf < 8; ++nf)
                    mma16816(acc[mf][nf], ah[mf], bh2[nf]);
        }
    }

    // epilogue: fp32 accumulators -> C
    const int lrow = lane >> 2;
    const int lcol = (lane & 3) * 2;
#pragma unroll
    for (int mf = 0; mf < 4; ++mf) {
#pragma unroll
        for (int nf = 0; nf < 8; ++nf) {
            int rm = m0 + mbase_w + mf * 16 + lrow;
            int cn = n0 + nbase_w + nf * 8 + lcol;
            float2 v0 = make_float2(acc[mf][nf][0], acc[mf][nf][1]);
            float2 v1 = make_float2(acc[mf][nf][2], acc[mf][nf][3]);
            *reinterpret_cast<float2*>(C + (size_t)rm * 1024 + cn) = v0;
            *reinterpret_cast<float2*>(C + (size_t)(rm + 8) * 1024 + cn) = v1;
        }
    }
}

// ---------------- p_attn partials: LN(K)^T LN(V) over an n-chunk -------------
__global__ __launch_bounds__(256)
void pattn_partial_kernel(const float* __restrict__ lnk_s, const float* __restrict__ lnk_b,
                          const float* __restrict__ lnv_s, const float* __restrict__ lnv_b)
{
    const int bh = blockIdx.x;
    const int chunk = blockIdx.y;
    const int b = bh >> 4, h = bh & 15;
    const int n0 = chunk * ROWS_PER_CHUNK;
    const long base = (long)b * (Ss * Ff) + (long)h * (512 * 1024);

    __shared__ float ks[16][64];
    __shared__ float vs[16][64];
    __shared__ float sks[64], skb[64], svs[64], svb[64];

    const int t = threadIdx.x;
    const int warp = t >> 5, lane = t & 31;

    if (t < 64) {
        sks[t] = lnk_s[h * 64 + t];
        skb[t] = lnk_b[h * 64 + t];
        svs[t] = lnv_s[h * 64 + t];
        svb[t] = lnv_b[h * 64 + t];
    }

    float acc[4][4];
#pragma unroll
    for (int i = 0; i < 4; i++)
#pragma unroll
        for (int j = 0; j < 4; j++) acc[i][j] = 0.f;

    const int td = (t >> 4) * 4;
    const int te = (t & 15) * 4;

    for (int r0 = 0; r0 < ROWS_PER_CHUNK; r0 += 16) {
        __syncthreads();
#pragma unroll
        for (int rr = 0; rr < 2; rr++) {
            int r = 2 * warp + rr;
            long off = base + (long)(n0 + r0 + r) * 64;

            float kx0 = gK[off + lane];
            float kx1 = gK[off + 32 + lane];
            float vx0 = gV[off + lane];
            float vx1 = gV[off + 32 + lane];

            float ksum = kx0 + kx1, ksq = kx0 * kx0 + kx1 * kx1;
            float vsum = vx0 + vx1, vsq = vx0 * vx0 + vx1 * vx1;
#pragma unroll
            for (int o = 16; o > 0; o >>= 1) {
                ksum += __shfl_xor_sync(0xffffffffu, ksum, o);
                ksq  += __shfl_xor_sync(0xffffffffu, ksq, o);
                vsum += __shfl_xor_sync(0xffffffffu, vsum, o);
                vsq  += __shfl_xor_sync(0xffffffffu, vsq, o);
            }
            float kmu = ksum * (1.f / 64.f);
            float kvar = ksq * (1.f / 64.f) - kmu * kmu;
            float krs = rsqrtf(kvar + 1e-6f);
            float vmu = vsum * (1.f / 64.f);
            float vvar = vsq * (1.f / 64.f) - vmu * vmu;
            float vrs = rsqrtf(vvar + 1e-6f);

            ks[r][lane]      = (kx0 - kmu) * krs * sks[lane]      + skb[lane];
            ks[r][lane + 32] = (kx1 - kmu) * krs * sks[lane + 32] + skb[lane + 32];
            vs[r][lane]      = (vx0 - vmu) * vrs * svs[lane]      + svb[lane];
            vs[r][lane + 32] = (vx1 - vmu) * vrs * svs[lane + 32] + svb[lane + 32];
        }
        __syncthreads();

#pragma unroll
        for (int r = 0; r < 16; r++) {
            float4 kq = *(const float4*)(&ks[r][td]);
            float4 vq = *(const float4*)(&vs[r][te]);
            float ka[4] = {kq.x, kq.y, kq.z, kq.w};
            float va[4] = {vq.x, vq.y, vq.z, vq.w};
#pragma unroll
            for (int i = 0; i < 4; i++)
#pragma unroll
                for (int j = 0; j < 4; j++)
                    acc[i][j] += ka[i] * va[j];
        }
    }

    float* p = gPpart + ((long)chunk * 64 + bh) * 4096;
#pragma unroll
    for (int i = 0; i < 4; i++)
#pragma unroll
        for (int j = 0; j < 4; j++)
            p[(td + i) * 64 + (te + j)] = acc[i][j];
}

__global__ void pattn_reduce_kernel(float* __restrict__ pout)
{
    int i = blockIdx.x * blockDim.x + threadIdx.x;
    if (i >= 64 * 4096) return;
    int bh = i >> 12;
    int idx = i & 4095;
    float s = 0.f;
#pragma unroll
    for (int c = 0; c < NCHUNK; c++)
        s += gPpart[((long)c * 64 + bh) * 4096 + idx];
    pout[i] = s * (1.f / 8192.f);
}

__global__ __launch_bounds__(256)
void out_kernel(const float* __restrict__ pattn, float* __restrict__ out)
{
    const int bh = blockIdx.y;
    const int b = bh >> 4, h = bh & 15;
    const int n0 = blockIdx.x * 64;

    __shared__ float ps[64][64];
    __shared__ float qs[64][68];

    const int t = threadIdx.x;
    const float* P = pattn + (long)bh * 4096;
    for (int i = t; i < 4096; i += 256)
        ps[i >> 6][i & 63] = P[i];

    const long base = (long)b * (Ss * Ff) + (long)h * 524288 + (long)n0 * 64;
#pragma unroll
    for (int it = 0; it < 4; it++) {
        int i = t * 4 + it * 1024;
        *(float4*)(&qs[i >> 6][i & 63]) = *(const float4*)(gQ + base + i);
    }
    __syncthreads();

    const int r  = t >> 2;
    const int eg = (t & 3) * 16;

    float acc[16];
#pragma unroll
    for (int j = 0; j < 16; j++) acc[j] = 0.f;

#pragma unroll
    for (int d = 0; d < 64; d++) {
        float q = qs[r][d];
#pragma unroll
        for (int j4 = 0; j4 < 4; j4++) {
            float4 pv = *(const float4*)(&ps[d][eg + j4 * 4]);
            acc[j4 * 4 + 0] += q * pv.x;
            acc[j4 * 4 + 1] += q * pv.y;
            acc[j4 * 4 + 2] += q * pv.z;
            acc[j4 * 4 + 3] += q * pv.w;
        }
    }

    float* o = out + base + (long)r * 64 + eg;
#pragma unroll
    for (int j4 = 0; j4 < 4; j4++)
        *(float4*)(o + j4 * 4) = make_float4(acc[j4 * 4 + 0], acc[j4 * 4 + 1],
                                             acc[j4 * 4 + 2], acc[j4 * 4 + 3]);
}

// ---------------- launch ----------------------------------------------------
extern "C" void kernel_launch(void* const* d_in, const int* in_sizes, int n_in,
                              void* d_out, int out_size)
{
    (void)in_sizes; (void)n_in; (void)out_size;
    const float* query = (const float*)d_in[0];
    const float* key   = (const float*)d_in[1];
    const float* value = (const float*)d_in[2];
    const float* Wq    = (const float*)d_in[3];
    const float* Wk    = (const float*)d_in[4];
    const float* Wv    = (const float*)d_in[5];
    const float* lnk_s = (const float*)d_in[6];
    const float* lnk_b = (const float*)d_in[7];
    const float* lnv_s = (const float*)d_in[8];
    const float* lnv_b = (const float*)d_in[9];

    float* out = (float*)d_out;
    float* pout = out + QELEMS;

    cudaFuncSetAttribute(gemm_mma_kernel, cudaFuncAttributeMaxDynamicSharedMemorySize,
                         2 * STAGE + 1024);

    convert_A_kernel<<<dim3(32768, 3), 256>>>(query, key, value);
    convert_W_kernel<<<dim3(32, 32, 3), 256>>>(Wq, Wk, Wv);

    gemm_mma_kernel<<<dim3(4, 256, 3), 256, 2 * STAGE + 1024>>>();

    dim3 pgrid(64, NCHUNK);
    pattn_partial_kernel<<<pgrid, 256>>>(lnk_s, lnk_b, lnv_s, lnv_b);
    pattn_reduce_kernel<<<(64 * 4096 + 255) / 256, 256>>>(pout);

    dim3 ogrid(8192 / 64, 64);
    out_kernel<<<ogrid, 256>>>(pout, out);
}

// round 7
// speedup vs baseline: 3.7523x; 1.1321x over previous
#include <cuda_runtime.h>
#include <cuda_fp16.h>
#include <cstdint>

// ---------------- problem constants ----------------
static constexpr int Bb = 4, Ss = 8192, Ff = 1024, Hh = 16, Dd = 64;
static constexpr int Mm = Bb * Ss;              // 32768
static constexpr int Kk = 1024, Nn = 1024;
static constexpr long QELEMS = (long)Mm * Ff;   // 33554432
static constexpr int NCHUNK = 32;
static constexpr int ROWS_PER_CHUNK = 8192 / NCHUNK;  // 256

// ---------------- scratch (device globals) ----------------
__device__ float gQ[33554432];                  // Q projection, fp32 (for out_kernel)
__device__ __half gKh[33554432];                // K projection, fp16 (for pattn)
__device__ __half gVh[33554432];                // V projection, fp16 (for pattn)
__device__ float gPpart[(long)NCHUNK * 64 * 4096];
__device__ __half gAh[3L * 33554432];
__device__ __half gWt[3L * 1048576];            // W^T: [n][k], k contiguous, fp16

// ---------------- helpers ----------------
__device__ __forceinline__ uint32_t smem_u32(const void* p) {
    uint32_t a;
    asm("{ .reg .u64 t; cvta.to.shared.u64 t, %1; cvt.u32.u64 %0, t; }" : "=r"(a) : "l"(p));
    return a;
}
// Swizzle<3,4,3> for 128B rows: XOR 16B-chunk bits [4:6] with row bits [7:9]
__device__ __forceinline__ uint32_t SZ128(uint32_t a) { return a ^ ((a >> 3) & 0x70u); }

__device__ __forceinline__ void cp16(uint32_t dst, const void* src) {
    asm volatile("cp.async.cg.shared.global [%0], [%1], 16;\n" :: "r"(dst), "l"(src));
}
__device__ __forceinline__ void cp_commit() { asm volatile("cp.async.commit_group;\n"); }
template<int N> __device__ __forceinline__ void cp_wait() {
    asm volatile("cp.async.wait_group %0;\n" :: "n"(N));
}
__device__ __forceinline__ void ldm4(uint32_t* r, uint32_t addr) {
    asm volatile("ldmatrix.sync.aligned.m8n8.x4.shared.b16 {%0,%1,%2,%3}, [%4];"
                 : "=r"(r[0]), "=r"(r[1]), "=r"(r[2]), "=r"(r[3]) : "r"(addr));
}
__device__ __forceinline__ void mma16816(float* d, const uint32_t* a, const uint32_t* b) {
    asm volatile(
        "mma.sync.aligned.m16n8k16.row.col.f32.f16.f16.f32 "
        "{%0,%1,%2,%3}, {%4,%5,%6,%7}, {%8,%9}, {%0,%1,%2,%3};"
        : "+f"(d[0]), "+f"(d[1]), "+f"(d[2]), "+f"(d[3])
        : "r"(a[0]), "r"(a[1]), "r"(a[2]), "r"(a[3]), "r"(b[0]), "r"(b[1]));
}

// ---------------- conversion prepasses ----------------
__global__ __launch_bounds__(256)
void convert_A_kernel(const float* __restrict__ q, const float* __restrict__ k,
                      const float* __restrict__ v)
{
    const int which = blockIdx.y;
    const float* src = (which == 0) ? q : (which == 1) ? k : v;
    __half* hi = gAh + (size_t)which * 33554432;

    size_t i4 = (size_t)blockIdx.x * blockDim.x + threadIdx.x;   // 0..8388607
    float4 x = reinterpret_cast<const float4*>(src)[i4];

    __half2 uh0 = __halves2half2(__float2half_rn(x.x), __float2half_rn(x.y));
    __half2 uh1 = __halves2half2(__float2half_rn(x.z), __float2half_rn(x.w));
    uint2 uh;
    uh.x = *reinterpret_cast<unsigned*>(&uh0);
    uh.y = *reinterpret_cast<unsigned*>(&uh1);
    reinterpret_cast<uint2*>(hi)[i4] = uh;
}

__global__ __launch_bounds__(256)
void convert_W_kernel(const float* __restrict__ wq, const float* __restrict__ wk,
                      const float* __restrict__ wv)
{
    const int which = blockIdx.z;
    const float* W = (which == 0) ? wq : (which == 1) ? wk : wv;
    __half* hi = gWt + (size_t)which * 1048576;

    __shared__ float tile[32][33];
    const int bx = blockIdx.x * 32;   // n block
    const int by = blockIdx.y * 32;   // k block
    const int tx = threadIdx.x & 31;
    const int ty = threadIdx.x >> 5;  // 0..7

#pragma unroll
    for (int i = 0; i < 32; i += 8)
        tile[ty + i][tx] = W[(size_t)(by + ty + i) * 1024 + bx + tx];
    __syncthreads();
#pragma unroll
    for (int i = 0; i < 32; i += 8) {
        float x = tile[tx][ty + i];                 // = W[by+tx][bx+ty+i]
        size_t o = (size_t)(bx + ty + i) * 1024 + by + tx;   // Wt[n][k]
        hi[o] = __float2half_rn(x);
    }
}

// ---------------- HMMA GEMM: C[M,N] = A @ W  (fp16, 3-stage) -----------------
// Tile 128x256xK64, 8 warps (2m x 4n, 64x64 warp tiles), 3-stage cp.async.
// smem/stage: A 16K | B 32K = 48K; three stages = 144K.
static constexpr int STAGE = 49152;
static constexpr int NCH = 16;        // 1024 / 64

__global__ __launch_bounds__(256, 1)
void gemm_mma_kernel()
{
    extern __shared__ char smem[];
    const int which = blockIdx.z;
    const int n0 = blockIdx.x * 256;
    const int m0 = blockIdx.y * 128;
    const int tid = threadIdx.x;
    const int wid = tid >> 5, lane = tid & 31;

    const uint32_t tiles = (smem_u32(smem) + 1023) & ~1023u;

    const __half* Ah = gAh + (size_t)which * 33554432;
    const __half* Bp = gWt + (size_t)which * 1048576;

    const int mbase_w = (wid & 1) * 64;
    const int nbase_w = (wid >> 1) * 64;

    float acc[4][8][4];
#pragma unroll
    for (int i = 0; i < 4; i++)
#pragma unroll
        for (int j = 0; j < 8; j++)
#pragma unroll
            for (int q = 0; q < 4; q++) acc[i][j][q] = 0.f;

    auto load_chunk = [&](int buf, int c) {
        const uint32_t base = tiles + buf * STAGE;
        const int k0 = c * 64;
#pragma unroll
        for (int i = tid; i < 1024; i += 256) {         // A: 128 rows x 8 chunks
            int r = i >> 3, c8 = i & 7;
            size_t gb = ((size_t)(m0 + r) * 1024 + k0 + c8 * 8) * 2;
            uint32_t d = SZ128((uint32_t)(r * 128 + c8 * 16));
            cp16(base + d, (const char*)Ah + gb);
        }
#pragma unroll
        for (int i = tid; i < 2048; i += 256) {         // B: 256 rows x 8 chunks
            int r = i >> 3, c8 = i & 7;
            size_t gb = ((size_t)(n0 + r) * 1024 + k0 + c8 * 8) * 2;
            uint32_t d = SZ128((uint32_t)(r * 128 + c8 * 16));
            cp16(base + 16384 + d, (const char*)Bp + gb);
        }
        cp_commit();
    };

    load_chunk(0, 0);
    load_chunk(1, 1);

    // lane-invariant pieces of ldmatrix addressing
    const int arow = (lane & 7) + ((lane >> 3) & 1) * 8;
    const int aoff = ((lane >> 4) & 1) * 16;
    const int brow = (lane & 7) + ((lane >> 4) & 1) * 8;
    const int boff = ((lane >> 3) & 1) * 16;

    int buf = 0;
    for (int c = 0; c < NCH; ++c) {
        if (c < NCH - 1) cp_wait<1>(); else cp_wait<0>();
        __syncthreads();
        if (c + 2 < NCH) load_chunk((buf + 2) % 3, c + 2);

        const uint32_t ab = tiles + buf * STAGE;
        const uint32_t bb = ab + 16384;

#pragma unroll
        for (int s = 0; s < 4; ++s) {
            uint32_t ah[4][4], bh2[8][2];
#pragma unroll
            for (int bg = 0; bg < 4; ++bg) {
                uint32_t u = SZ128((uint32_t)((nbase_w + bg * 16 + brow) * 128 + s * 32 + boff));
                uint32_t r[4];
                ldm4(r, bb + u);
                bh2[2 * bg][0] = r[0]; bh2[2 * bg][1] = r[1];
                bh2[2 * bg + 1][0] = r[2]; bh2[2 * bg + 1][1] = r[3];
            }
#pragma unroll
            for (int mf = 0; mf < 4; ++mf) {
                uint32_t u = SZ128((uint32_t)((mbase_w + mf * 16 + arow) * 128 + s * 32 + aoff));
                ldm4(ah[mf], ab + u);
            }
#pragma unroll
            for (int mf = 0; mf < 4; ++mf)
#pragma unroll
                for (int nf = 0; nf < 8; ++nf)
                    mma16816(acc[mf][nf], ah[mf], bh2[nf]);
        }
        buf = (buf + 1) % 3;
    }

    // epilogue: Q -> fp32; K,V -> fp16
    const int lrow = lane >> 2;
    const int lcol = (lane & 3) * 2;
    if (which == 0) {
#pragma unroll
        for (int mf = 0; mf < 4; ++mf)
#pragma unroll
            for (int nf = 0; nf < 8; ++nf) {
                int rm = m0 + mbase_w + mf * 16 + lrow;
                int cn = n0 + nbase_w + nf * 8 + lcol;
                *reinterpret_cast<float2*>(gQ + (size_t)rm * 1024 + cn) =
                    make_float2(acc[mf][nf][0], acc[mf][nf][1]);
                *reinterpret_cast<float2*>(gQ + (size_t)(rm + 8) * 1024 + cn) =
                    make_float2(acc[mf][nf][2], acc[mf][nf][3]);
            }
    } else {
        __half* Ch = (which == 1) ? gKh : gVh;
#pragma unroll
        for (int mf = 0; mf < 4; ++mf)
#pragma unroll
            for (int nf = 0; nf < 8; ++nf) {
                int rm = m0 + mbase_w + mf * 16 + lrow;
                int cn = n0 + nbase_w + nf * 8 + lcol;
                *reinterpret_cast<__half2*>(Ch + (size_t)rm * 1024 + cn) =
                    __floats2half2_rn(acc[mf][nf][0], acc[mf][nf][1]);
                *reinterpret_cast<__half2*>(Ch + (size_t)(rm + 8) * 1024 + cn) =
                    __floats2half2_rn(acc[mf][nf][2], acc[mf][nf][3]);
            }
    }
}

// ---------------- p_attn partials: LN(K)^T LN(V) over an n-chunk (fp16) ------
__global__ __launch_bounds__(256)
void pattn_partial_kernel(const float* __restrict__ lnk_s, const float* __restrict__ lnk_b,
                          const float* __restrict__ lnv_s, const float* __restrict__ lnv_b)
{
    const int bh = blockIdx.x;
    const int chunk = blockIdx.y;
    const int b = bh >> 4, h = bh & 15;
    const int n0 = chunk * ROWS_PER_CHUNK;
    const long base = (long)b * (Ss * Ff) + (long)h * (512 * 1024);

    __shared__ __half2 ksh[16][32];
    __shared__ __half2 vsh[16][32];
    __shared__ float sks[64], skb[64], svs[64], svb[64];

    const int t = threadIdx.x;
    const int warp = t >> 5, lane = t & 31;

    if (t < 64) {
        sks[t] = lnk_s[h * 64 + t];
        skb[t] = lnk_b[h * 64 + t];
        svs[t] = lnv_s[h * 64 + t];
        svb[t] = lnv_b[h * 64 + t];
    }

    float acc[4][4];
#pragma unroll
    for (int i = 0; i < 4; i++)
#pragma unroll
        for (int j = 0; j < 4; j++) acc[i][j] = 0.f;

    const int td = (t >> 4) * 4;   // d offset
    const int te = (t & 15) * 4;   // e offset

    for (int r0 = 0; r0 < ROWS_PER_CHUNK; r0 += 16) {
        __syncthreads();
#pragma unroll
        for (int rr = 0; rr < 2; rr++) {
            int r = 2 * warp + rr;
            long off = base + (long)(n0 + r0 + r) * 64;

            __half2 kk = reinterpret_cast<const __half2*>(gKh + off)[lane];
            __half2 vv = reinterpret_cast<const __half2*>(gVh + off)[lane];
            float2 kf = __half22float2(kk);
            float2 vf = __half22float2(vv);

            float ksum = kf.x + kf.y, ksq = kf.x * kf.x + kf.y * kf.y;
            float vsum = vf.x + vf.y, vsq = vf.x * vf.x + vf.y * vf.y;
#pragma unroll
            for (int o = 16; o > 0; o >>= 1) {
                ksum += __shfl_xor_sync(0xffffffffu, ksum, o);
                ksq  += __shfl_xor_sync(0xffffffffu, ksq, o);
                vsum += __shfl_xor_sync(0xffffffffu, vsum, o);
                vsq  += __shfl_xor_sync(0xffffffffu, vsq, o);
            }
            float kmu = ksum * (1.f / 64.f);
            float kvar = ksq * (1.f / 64.f) - kmu * kmu;
            float krs = rsqrtf(kvar + 1e-6f);
            float vmu = vsum * (1.f / 64.f);
            float vvar = vsq * (1.f / 64.f) - vmu * vmu;
            float vrs = rsqrtf(vvar + 1e-6f);

            float nk0 = (kf.x - kmu) * krs * sks[2 * lane]     + skb[2 * lane];
            float nk1 = (kf.y - kmu) * krs * sks[2 * lane + 1] + skb[2 * lane + 1];
            float nv0 = (vf.x - vmu) * vrs * svs[2 * lane]     + svb[2 * lane];
            float nv1 = (vf.y - vmu) * vrs * svs[2 * lane + 1] + svb[2 * lane + 1];

            ksh[r][lane] = __floats2half2_rn(nk0, nk1);
            vsh[r][lane] = __floats2half2_rn(nv0, nv1);
        }
        __syncthreads();

#pragma unroll
        for (int r = 0; r < 16; r++) {
            uint2 ku = *reinterpret_cast<const uint2*>(&ksh[r][td >> 1]);
            uint2 vu = *reinterpret_cast<const uint2*>(&vsh[r][te >> 1]);
            float2 k01 = __half22float2(*reinterpret_cast<__half2*>(&ku.x));
            float2 k23 = __half22float2(*reinterpret_cast<__half2*>(&ku.y));
            float2 v01 = __half22float2(*reinterpret_cast<__half2*>(&vu.x));
            float2 v23 = __half22float2(*reinterpret_cast<__half2*>(&vu.y));
            float ka[4] = {k01.x, k01.y, k23.x, k23.y};
            float va[4] = {v01.x, v01.y, v23.x, v23.y};
#pragma unroll
            for (int i = 0; i < 4; i++)
#pragma unroll
                for (int j = 0; j < 4; j++)
                    acc[i][j] += ka[i] * va[j];
        }
    }

    float* p = gPpart + ((long)chunk * 64 + bh) * 4096;
#pragma unroll
    for (int i = 0; i < 4; i++)
#pragma unroll
        for (int j = 0; j < 4; j++)
            p[(td + i) * 64 + (te + j)] = acc[i][j];
}

__global__ void pattn_reduce_kernel(float* __restrict__ pout)
{
    int i = blockIdx.x * blockDim.x + threadIdx.x;
    if (i >= 64 * 4096) return;
    int bh = i >> 12;
    int idx = i & 4095;
    float s = 0.f;
#pragma unroll
    for (int c = 0; c < NCHUNK; c++)
        s += gPpart[((long)c * 64 + bh) * 4096 + idx];
    pout[i] = s * (1.f / 8192.f);
}

__global__ __launch_bounds__(256)
void out_kernel(const float* __restrict__ pattn, float* __restrict__ out)
{
    const int bh = blockIdx.y;
    const int b = bh >> 4, h = bh & 15;
    const int n0 = blockIdx.x * 64;

    __shared__ float ps[64][64];
    __shared__ float qs[64][68];

    const int t = threadIdx.x;
    const float* P = pattn + (long)bh * 4096;
    for (int i = t; i < 4096; i += 256)
        ps[i >> 6][i & 63] = P[i];

    const long base = (long)b * (Ss * Ff) + (long)h * 524288 + (long)n0 * 64;
#pragma unroll
    for (int it = 0; it < 4; it++) {
        int i = t * 4 + it * 1024;
        *(float4*)(&qs[i >> 6][i & 63]) = *(const float4*)(gQ + base + i);
    }
    __syncthreads();

    const int r  = t >> 2;
    const int eg = (t & 3) * 16;

    float acc[16];
#pragma unroll
    for (int j = 0; j < 16; j++) acc[j] = 0.f;

#pragma unroll
    for (int d = 0; d < 64; d++) {
        float q = qs[r][d];
#pragma unroll
        for (int j4 = 0; j4 < 4; j4++) {
            float4 pv = *(const float4*)(&ps[d][eg + j4 * 4]);
            acc[j4 * 4 + 0] += q * pv.x;
            acc[j4 * 4 + 1] += q * pv.y;
            acc[j4 * 4 + 2] += q * pv.z;
            acc[j4 * 4 + 3] += q * pv.w;
        }
    }

    float* o = out + base + (long)r * 64 + eg;
#pragma unroll
    for (int j4 = 0; j4 < 4; j4++)
        *(float4*)(o + j4 * 4) = make_float4(acc[j4 * 4 + 0], acc[j4 * 4 + 1],
                                             acc[j4 * 4 + 2], acc[j4 * 4 + 3]);
}

// ---------------- launch ----------------------------------------------------
extern "C" void kernel_launch(void* const* d_in, const int* in_sizes, int n_in,
                              void* d_out, int out_size)
{
    (void)in_sizes; (void)n_in; (void)out_size;
    const float* query = (const float*)d_in[0];
    const float* key   = (const float*)d_in[1];
    const float* value = (const float*)d_in[2];
    const float* Wq    = (const float*)d_in[3];
    const float* Wk    = (const float*)d_in[4];
    const float* Wv    = (const float*)d_in[5];
    const float* lnk_s = (const float*)d_in[6];
    const float* lnk_b = (const float*)d_in[7];
    const float* lnv_s = (const float*)d_in[8];
    const float* lnv_b = (const float*)d_in[9];

    float* out = (float*)d_out;
    float* pout = out + QELEMS;

    cudaFuncSetAttribute(gemm_mma_kernel, cudaFuncAttributeMaxDynamicSharedMemorySize,
                         3 * STAGE + 1024);

    convert_A_kernel<<<dim3(32768, 3), 256>>>(query, key, value);
    convert_W_kernel<<<dim3(32, 32, 3), 256>>>(Wq, Wk, Wv);

    gemm_mma_kernel<<<dim3(4, 256, 3), 256, 3 * STAGE + 1024>>>();

    dim3 pgrid(64, NCHUNK);
    pattn_partial_kernel<<<pgrid, 256>>>(lnk_s, lnk_b, lnv_s, lnv_b);
    pattn_reduce_kernel<<<(64 * 4096 + 255) / 256, 256>>>(pout);

    dim3 ogrid(8192 / 64, 64);
    out_kernel<<<ogrid, 256>>>(pout, out);
}

// round 8
// speedup vs baseline: 4.0552x; 1.0807x over previous
#include <cuda_runtime.h>
#include <cuda_fp16.h>
#include <cstdint>

// ---------------- problem constants ----------------
static constexpr int Bb = 4, Ss = 8192, Ff = 1024, Hh = 16, Dd = 64;
static constexpr int Mm = Bb * Ss;              // 32768
static constexpr int Kk = 1024, Nn = 1024;
static constexpr long QELEMS = (long)Mm * Ff;   // 33554432
static constexpr int NCHUNK = 32;
static constexpr int ROWS_PER_CHUNK = 8192 / NCHUNK;  // 256

// ---------------- scratch (device globals) ----------------
__device__ float gQ[33554432];                  // Q projection, fp32 (for out_kernel)
__device__ __half gKh[33554432];                // K projection, fp16 (for pattn)
__device__ __half gVh[33554432];                // V projection, fp16 (for pattn)
__device__ float gPpart[(long)NCHUNK * 64 * 4096];
__device__ __half gAh[3L * 33554432];
__device__ __half gWt[3L * 1048576];            // W^T: [n][k], k contiguous, fp16

// ---------------- helpers ----------------
__device__ __forceinline__ uint32_t smem_u32(const void* p) {
    uint32_t a;
    asm("{ .reg .u64 t; cvta.to.shared.u64 t, %1; cvt.u32.u64 %0, t; }" : "=r"(a) : "l"(p));
    return a;
}
// Swizzle<3,4,3> for 128B rows: XOR 16B-chunk bits [4:6] with row bits [7:9]
__device__ __forceinline__ uint32_t SZ128(uint32_t a) { return a ^ ((a >> 3) & 0x70u); }

__device__ __forceinline__ void cp16(uint32_t dst, const void* src) {
    asm volatile("cp.async.cg.shared.global [%0], [%1], 16;\n" :: "r"(dst), "l"(src));
}
__device__ __forceinline__ void cp_commit() { asm volatile("cp.async.commit_group;\n"); }
template<int N> __device__ __forceinline__ void cp_wait() {
    asm volatile("cp.async.wait_group %0;\n" :: "n"(N));
}
__device__ __forceinline__ void ldm4(uint32_t* r, uint32_t addr) {
    asm volatile("ldmatrix.sync.aligned.m8n8.x4.shared.b16 {%0,%1,%2,%3}, [%4];"
                 : "=r"(r[0]), "=r"(r[1]), "=r"(r[2]), "=r"(r[3]) : "r"(addr));
}
__device__ __forceinline__ void ldm4t(uint32_t* r, uint32_t addr) {
    asm volatile("ldmatrix.sync.aligned.m8n8.x4.trans.shared.b16 {%0,%1,%2,%3}, [%4];"
                 : "=r"(r[0]), "=r"(r[1]), "=r"(r[2]), "=r"(r[3]) : "r"(addr));
}
__device__ __forceinline__ void mma16816(float* d, const uint32_t* a, const uint32_t* b) {
    asm volatile(
        "mma.sync.aligned.m16n8k16.row.col.f32.f16.f16.f32 "
        "{%0,%1,%2,%3}, {%4,%5,%6,%7}, {%8,%9}, {%0,%1,%2,%3};"
        : "+f"(d[0]), "+f"(d[1]), "+f"(d[2]), "+f"(d[3])
        : "r"(a[0]), "r"(a[1]), "r"(a[2]), "r"(a[3]), "r"(b[0]), "r"(b[1]));
}

// ---------------- conversion prepasses ----------------
__global__ __launch_bounds__(256)
void convert_A_kernel(const float* __restrict__ q, const float* __restrict__ k,
                      const float* __restrict__ v)
{
    const int which = blockIdx.y;
    const float* src = (which == 0) ? q : (which == 1) ? k : v;
    __half* hi = gAh + (size_t)which * 33554432;

    size_t i4 = (size_t)blockIdx.x * blockDim.x + threadIdx.x;   // 0..8388607
    float4 x = reinterpret_cast<const float4*>(src)[i4];

    __half2 uh0 = __halves2half2(__float2half_rn(x.x), __float2half_rn(x.y));
    __half2 uh1 = __halves2half2(__float2half_rn(x.z), __float2half_rn(x.w));
    uint2 uh;
    uh.x = *reinterpret_cast<unsigned*>(&uh0);
    uh.y = *reinterpret_cast<unsigned*>(&uh1);
    reinterpret_cast<uint2*>(hi)[i4] = uh;
}

__global__ __launch_bounds__(256)
void convert_W_kernel(const float* __restrict__ wq, const float* __restrict__ wk,
                      const float* __restrict__ wv)
{
    const int which = blockIdx.z;
    const float* W = (which == 0) ? wq : (which == 1) ? wk : wv;
    __half* hi = gWt + (size_t)which * 1048576;

    __shared__ float tile[32][33];
    const int bx = blockIdx.x * 32;   // n block
    const int by = blockIdx.y * 32;   // k block
    const int tx = threadIdx.x & 31;
    const int ty = threadIdx.x >> 5;  // 0..7

#pragma unroll
    for (int i = 0; i < 32; i += 8)
        tile[ty + i][tx] = W[(size_t)(by + ty + i) * 1024 + bx + tx];
    __syncthreads();
#pragma unroll
    for (int i = 0; i < 32; i += 8) {
        float x = tile[tx][ty + i];                 // = W[by+tx][bx+ty+i]
        size_t o = (size_t)(bx + ty + i) * 1024 + by + tx;   // Wt[n][k]
        hi[o] = __float2half_rn(x);
    }
}

// ---------------- HMMA GEMM: C[M,N] = A @ W  (fp16, 3-stage) -----------------
// Tile 128x256xK64, 8 warps (2m x 4n, 64x64 warp tiles), 3-stage cp.async.
// smem/stage: A 16K | B 32K = 48K; three stages = 144K.
static constexpr int STAGE = 49152;
static constexpr int NCH = 16;        // 1024 / 64

__global__ __launch_bounds__(256, 1)
void gemm_mma_kernel()
{
    extern __shared__ char smem[];
    const int which = blockIdx.z;
    const int n0 = blockIdx.x * 256;
    const int m0 = blockIdx.y * 128;
    const int tid = threadIdx.x;
    const int wid = tid >> 5, lane = tid & 31;

    const uint32_t tiles = (smem_u32(smem) + 1023) & ~1023u;

    const __half* Ah = gAh + (size_t)which * 33554432;
    const __half* Bp = gWt + (size_t)which * 1048576;

    const int mbase_w = (wid & 1) * 64;
    const int nbase_w = (wid >> 1) * 64;

    float acc[4][8][4];
#pragma unroll
    for (int i = 0; i < 4; i++)
#pragma unroll
        for (int j = 0; j < 8; j++)
#pragma unroll
            for (int q = 0; q < 4; q++) acc[i][j][q] = 0.f;

    auto load_chunk = [&](int buf, int c) {
        const uint32_t base = tiles + buf * STAGE;
        const int k0 = c * 64;
#pragma unroll
        for (int i = tid; i < 1024; i += 256) {         // A: 128 rows x 8 chunks
            int r = i >> 3, c8 = i & 7;
            size_t gb = ((size_t)(m0 + r) * 1024 + k0 + c8 * 8) * 2;
            uint32_t d = SZ128((uint32_t)(r * 128 + c8 * 16));
            cp16(base + d, (const char*)Ah + gb);
        }
#pragma unroll
        for (int i = tid; i < 2048; i += 256) {         // B: 256 rows x 8 chunks
            int r = i >> 3, c8 = i & 7;
            size_t gb = ((size_t)(n0 + r) * 1024 + k0 + c8 * 8) * 2;
            uint32_t d = SZ128((uint32_t)(r * 128 + c8 * 16));
            cp16(base + 16384 + d, (const char*)Bp + gb);
        }
        cp_commit();
    };

    load_chunk(0, 0);
    load_chunk(1, 1);

    // lane-invariant pieces of ldmatrix addressing
    const int arow = (lane & 7) + ((lane >> 3) & 1) * 8;
    const int aoff = ((lane >> 4) & 1) * 16;
    const int brow = (lane & 7) + ((lane >> 4) & 1) * 8;
    const int boff = ((lane >> 3) & 1) * 16;

    int buf = 0;
    for (int c = 0; c < NCH; ++c) {
        if (c < NCH - 1) cp_wait<1>(); else cp_wait<0>();
        __syncthreads();
        if (c + 2 < NCH) load_chunk((buf + 2) % 3, c + 2);

        const uint32_t ab = tiles + buf * STAGE;
        const uint32_t bb = ab + 16384;

#pragma unroll
        for (int s = 0; s < 4; ++s) {
            uint32_t ah[4][4], bh2[8][2];
#pragma unroll
            for (int bg = 0; bg < 4; ++bg) {
                uint32_t u = SZ128((uint32_t)((nbase_w + bg * 16 + brow) * 128 + s * 32 + boff));
                uint32_t r[4];
                ldm4(r, bb + u);
                bh2[2 * bg][0] = r[0]; bh2[2 * bg][1] = r[1];
                bh2[2 * bg + 1][0] = r[2]; bh2[2 * bg + 1][1] = r[3];
            }
#pragma unroll
            for (int mf = 0; mf < 4; ++mf) {
                uint32_t u = SZ128((uint32_t)((mbase_w + mf * 16 + arow) * 128 + s * 32 + aoff));
                ldm4(ah[mf], ab + u);
            }
#pragma unroll
            for (int mf = 0; mf < 4; ++mf)
#pragma unroll
                for (int nf = 0; nf < 8; ++nf)
                    mma16816(acc[mf][nf], ah[mf], bh2[nf]);
        }
        buf = (buf + 1) % 3;
    }

    // epilogue: Q -> fp32; K,V -> fp16
    const int lrow = lane >> 2;
    const int lcol = (lane & 3) * 2;
    if (which == 0) {
#pragma unroll
        for (int mf = 0; mf < 4; ++mf)
#pragma unroll
            for (int nf = 0; nf < 8; ++nf) {
                int rm = m0 + mbase_w + mf * 16 + lrow;
                int cn = n0 + nbase_w + nf * 8 + lcol;
                *reinterpret_cast<float2*>(gQ + (size_t)rm * 1024 + cn) =
                    make_float2(acc[mf][nf][0], acc[mf][nf][1]);
                *reinterpret_cast<float2*>(gQ + (size_t)(rm + 8) * 1024 + cn) =
                    make_float2(acc[mf][nf][2], acc[mf][nf][3]);
            }
    } else {
        __half* Ch = (which == 1) ? gKh : gVh;
#pragma unroll
        for (int mf = 0; mf < 4; ++mf)
#pragma unroll
            for (int nf = 0; nf < 8; ++nf) {
                int rm = m0 + mbase_w + mf * 16 + lrow;
                int cn = n0 + nbase_w + nf * 8 + lcol;
                *reinterpret_cast<__half2*>(Ch + (size_t)rm * 1024 + cn) =
                    __floats2half2_rn(acc[mf][nf][0], acc[mf][nf][1]);
                *reinterpret_cast<__half2*>(Ch + (size_t)(rm + 8) * 1024 + cn) =
                    __floats2half2_rn(acc[mf][nf][2], acc[mf][nf][3]);
            }
    }
}

// ---------------- p_attn partials: LN(K)^T LN(V), HMMA consumer --------------
// Block: 256 threads. LN producer stages 16 rows of LN'd K,V (fp16, 72-half
// padded rows -> LDSM conflict-free); 8 warps consume via ldmatrix.trans +
// mma, each owning a 16(d) x 32(e) tile of the 64x64 output.
__global__ __launch_bounds__(256)
void pattn_partial_kernel(const float* __restrict__ lnk_s, const float* __restrict__ lnk_b,
                          const float* __restrict__ lnv_s, const float* __restrict__ lnv_b)
{
    const int bh = blockIdx.x;
    const int chunk = blockIdx.y;
    const int b = bh >> 4, h = bh & 15;
    const int n0 = chunk * ROWS_PER_CHUNK;
    const long base = (long)b * (Ss * Ff) + (long)h * (512 * 1024);

    __shared__ __half ksh[16][72];
    __shared__ __half vsh[16][72];
    __shared__ float sks[64], skb[64], svs[64], svb[64];

    const int t = threadIdx.x;
    const int warp = t >> 5, lane = t & 31;

    if (t < 64) {
        sks[t] = lnk_s[h * 64 + t];
        skb[t] = lnk_b[h * 64 + t];
        svs[t] = lnv_s[h * 64 + t];
        svb[t] = lnv_b[h * 64 + t];
    }

    // warp output tile: d0 = (warp>>1)*16, e0 = (warp&1)*32
    const int d0 = (warp >> 1) * 16;
    const int e0 = (warp & 1) * 32;

    // ldmatrix.trans addresses (constant across iterations)
    // A (from ksh): frag (m=d, k=r): r=(lane&7)+((lane>>4)&1)*8, col=d0+((lane>>3)&1)*8
    const uint32_t aaddr = smem_u32(
        &ksh[(lane & 7) + ((lane >> 4) & 1) * 8][d0 + ((lane >> 3) & 1) * 8]);
    // B (from vsh): frag (n=e, k=r): r=(lane&7)+((lane>>3)&1)*8, col=e+((lane>>4)&1)*8
    const uint32_t baddr0 = smem_u32(
        &vsh[(lane & 7) + ((lane >> 3) & 1) * 8][e0 + ((lane >> 4) & 1) * 8]);
    const uint32_t baddr1 = baddr0 + 16 * 2;   // e0+16 group

    float acc[4][4];
#pragma unroll
    for (int i = 0; i < 4; i++)
#pragma unroll
        for (int j = 0; j < 4; j++) acc[i][j] = 0.f;

    for (int r0 = 0; r0 < ROWS_PER_CHUNK; r0 += 16) {
        __syncthreads();   // smem tiles free for reuse
#pragma unroll
        for (int rr = 0; rr < 2; rr++) {
            int r = 2 * warp + rr;
            long off = base + (long)(n0 + r0 + r) * 64;

            __half2 kk = reinterpret_cast<const __half2*>(gKh + off)[lane];
            __half2 vv = reinterpret_cast<const __half2*>(gVh + off)[lane];
            float2 kf = __half22float2(kk);
            float2 vf = __half22float2(vv);

            float ksum = kf.x + kf.y, ksq = kf.x * kf.x + kf.y * kf.y;
            float vsum = vf.x + vf.y, vsq = vf.x * vf.x + vf.y * vf.y;
#pragma unroll
            for (int o = 16; o > 0; o >>= 1) {
                ksum += __shfl_xor_sync(0xffffffffu, ksum, o);
                ksq  += __shfl_xor_sync(0xffffffffu, ksq, o);
                vsum += __shfl_xor_sync(0xffffffffu, vsum, o);
                vsq  += __shfl_xor_sync(0xffffffffu, vsq, o);
            }
            float kmu = ksum * (1.f / 64.f);
            float kvar = ksq * (1.f / 64.f) - kmu * kmu;
            float krs = rsqrtf(kvar + 1e-6f);
            float vmu = vsum * (1.f / 64.f);
            float vvar = vsq * (1.f / 64.f) - vmu * vmu;
            float vrs = rsqrtf(vvar + 1e-6f);

            float nk0 = (kf.x - kmu) * krs * sks[2 * lane]     + skb[2 * lane];
            float nk1 = (kf.y - kmu) * krs * sks[2 * lane + 1] + skb[2 * lane + 1];
            float nv0 = (vf.x - vmu) * vrs * svs[2 * lane]     + svb[2 * lane];
            float nv1 = (vf.y - vmu) * vrs * svs[2 * lane + 1] + svb[2 * lane + 1];

            *reinterpret_cast<__half2*>(&ksh[r][2 * lane]) = __floats2half2_rn(nk0, nk1);
            *reinterpret_cast<__half2*>(&vsh[r][2 * lane]) = __floats2half2_rn(nv0, nv1);
        }
        __syncthreads();   // tiles ready

        uint32_t a[4], bq0[4], bq1[4];
        ldm4t(a, aaddr);
        ldm4t(bq0, baddr0);
        ldm4t(bq1, baddr1);
        uint32_t bfr[4][2] = {{bq0[0], bq0[1]}, {bq0[2], bq0[3]},
                              {bq1[0], bq1[1]}, {bq1[2], bq1[3]}};
#pragma unroll
        for (int nf = 0; nf < 4; ++nf)
            mma16816(acc[nf], a, bfr[nf]);
    }

    float* p = gPpart + ((long)chunk * 64 + bh) * 4096;
    const int lrow = lane >> 2;
    const int lcol = (lane & 3) * 2;
#pragma unroll
    for (int nf = 0; nf < 4; ++nf) {
        int e = e0 + nf * 8 + lcol;
        *reinterpret_cast<float2*>(p + (d0 + lrow) * 64 + e) =
            make_float2(acc[nf][0], acc[nf][1]);
        *reinterpret_cast<float2*>(p + (d0 + lrow + 8) * 64 + e) =
            make_float2(acc[nf][2], acc[nf][3]);
    }
}

__global__ void pattn_reduce_kernel(float* __restrict__ pout)
{
    int i = blockIdx.x * blockDim.x + threadIdx.x;
    if (i >= 64 * 4096) return;
    int bh = i >> 12;
    int idx = i & 4095;
    float s = 0.f;
#pragma unroll
    for (int c = 0; c < NCHUNK; c++)
        s += gPpart[((long)c * 64 + bh) * 4096 + idx];
    pout[i] = s * (1.f / 8192.f);
}

__global__ __launch_bounds__(256)
void out_kernel(const float* __restrict__ pattn, float* __restrict__ out)
{
    const int bh = blockIdx.y;
    const int b = bh >> 4, h = bh & 15;
    const int n0 = blockIdx.x * 64;

    __shared__ float ps[64][64];
    __shared__ float qs[64][68];

    const int t = threadIdx.x;
    const float* P = pattn + (long)bh * 4096;
    for (int i = t; i < 4096; i += 256)
        ps[i >> 6][i & 63] = P[i];

    const long base = (long)b * (Ss * Ff) + (long)h * 524288 + (long)n0 * 64;
#pragma unroll
    for (int it = 0; it < 4; it++) {
        int i = t * 4 + it * 1024;
        *(float4*)(&qs[i >> 6][i & 63]) = *(const float4*)(gQ + base + i);
    }
    __syncthreads();

    const int r  = t >> 2;
    const int eg = (t & 3) * 16;

    float acc[16];
#pragma unroll
    for (int j = 0; j < 16; j++) acc[j] = 0.f;

#pragma unroll
    for (int d = 0; d < 64; d++) {
        float q = qs[r][d];
#pragma unroll
        for (int j4 = 0; j4 < 4; j4++) {
            float4 pv = *(const float4*)(&ps[d][eg + j4 * 4]);
            acc[j4 * 4 + 0] += q * pv.x;
            acc[j4 * 4 + 1] += q * pv.y;
            acc[j4 * 4 + 2] += q * pv.z;
            acc[j4 * 4 + 3] += q * pv.w;
        }
    }

    float* o = out + base + (long)r * 64 + eg;
#pragma unroll
    for (int j4 = 0; j4 < 4; j4++)
        *(float4*)(o + j4 * 4) = make_float4(acc[j4 * 4 + 0], acc[j4 * 4 + 1],
                                             acc[j4 * 4 + 2], acc[j4 * 4 + 3]);
}

// ---------------- launch ----------------------------------------------------
extern "C" void kernel_launch(void* const* d_in, const int* in_sizes, int n_in,
                              void* d_out, int out_size)
{
    (void)in_sizes; (void)n_in; (void)out_size;
    const float* query = (const float*)d_in[0];
    const float* key   = (const float*)d_in[1];
    const float* value = (const float*)d_in[2];
    const float* Wq    = (const float*)d_in[3];
    const float* Wk    = (const float*)d_in[4];
    const float* Wv    = (const float*)d_in[5];
    const float* lnk_s = (const float*)d_in[6];
    const float* lnk_b = (const float*)d_in[7];
    const float* lnv_s = (const float*)d_in[8];
    const float* lnv_b = (const float*)d_in[9];

    float* out = (float*)d_out;
    float* pout = out + QELEMS;

    cudaFuncSetAttribute(gemm_mma_kernel, cudaFuncAttributeMaxDynamicSharedMemorySize,
                         3 * STAGE + 1024);

    convert_A_kernel<<<dim3(32768, 3), 256>>>(query, key, value);
    convert_W_kernel<<<dim3(32, 32, 3), 256>>>(Wq, Wk, Wv);

    gemm_mma_kernel<<<dim3(4, 256, 3), 256, 3 * STAGE + 1024>>>();

    dim3 pgrid(64, NCHUNK);
    pattn_partial_kernel<<<pgrid, 256>>>(lnk_s, lnk_b, lnv_s, lnv_b);
    pattn_reduce_kernel<<<(64 * 4096 + 255) / 256, 256>>>(pout);

    dim3 ogrid(8192 / 64, 64);
    out_kernel<<<ogrid, 256>>>(pout, out);
}

// round 9
// speedup vs baseline: 4.1342x; 1.0195x over previous
#include <cuda_runtime.h>
#include <cuda_fp16.h>
#include <cstdint>

// ---------------- problem constants ----------------
static constexpr int Bb = 4, Ss = 8192, Ff = 1024, Hh = 16, Dd = 64;
static constexpr int Mm = Bb * Ss;              // 32768
static constexpr int Kk = 1024, Nn = 1024;
static constexpr long QELEMS = (long)Mm * Ff;   // 33554432
static constexpr int NCHUNK = 32;
static constexpr int ROWS_PER_CHUNK = 8192 / NCHUNK;  // 256

// ---------------- scratch (device globals) ----------------
__device__ float gQ[33554432];                  // Q projection, fp32 (for out_kernel)
__device__ __half gKh[33554432];                // K projection, fp16 (for pattn)
__device__ __half gVh[33554432];                // V projection, fp16 (for pattn)
__device__ float gPpart[(long)NCHUNK * 64 * 4096];
__device__ __half gAh[3L * 33554432];
__device__ __half gWt[3L * 1048576];            // W^T: [n][k], k contiguous, fp16

// ---------------- helpers ----------------
__device__ __forceinline__ uint32_t smem_u32(const void* p) {
    uint32_t a;
    asm("{ .reg .u64 t; cvta.to.shared.u64 t, %1; cvt.u32.u64 %0, t; }" : "=r"(a) : "l"(p));
    return a;
}
// Swizzle<3,4,3> for 128B rows: XOR 16B-chunk bits [4:6] with row bits [7:9]
__device__ __forceinline__ uint32_t SZ128(uint32_t a) { return a ^ ((a >> 3) & 0x70u); }

__device__ __forceinline__ void cp16(uint32_t dst, const void* src) {
    asm volatile("cp.async.cg.shared.global [%0], [%1], 16;\n" :: "r"(dst), "l"(src));
}
__device__ __forceinline__ void cp_commit() { asm volatile("cp.async.commit_group;\n"); }
template<int N> __device__ __forceinline__ void cp_wait() {
    asm volatile("cp.async.wait_group %0;\n" :: "n"(N));
}
__device__ __forceinline__ void ldm4(uint32_t* r, uint32_t addr) {
    asm volatile("ldmatrix.sync.aligned.m8n8.x4.shared.b16 {%0,%1,%2,%3}, [%4];"
                 : "=r"(r[0]), "=r"(r[1]), "=r"(r[2]), "=r"(r[3]) : "r"(addr));
}
__device__ __forceinline__ void ldm4t(uint32_t* r, uint32_t addr) {
    asm volatile("ldmatrix.sync.aligned.m8n8.x4.trans.shared.b16 {%0,%1,%2,%3}, [%4];"
                 : "=r"(r[0]), "=r"(r[1]), "=r"(r[2]), "=r"(r[3]) : "r"(addr));
}
__device__ __forceinline__ void mma16816(float* d, const uint32_t* a, const uint32_t* b) {
    asm volatile(
        "mma.sync.aligned.m16n8k16.row.col.f32.f16.f16.f32 "
        "{%0,%1,%2,%3}, {%4,%5,%6,%7}, {%8,%9}, {%0,%1,%2,%3};"
        : "+f"(d[0]), "+f"(d[1]), "+f"(d[2]), "+f"(d[3])
        : "r"(a[0]), "r"(a[1]), "r"(a[2]), "r"(a[3]), "r"(b[0]), "r"(b[1]));
}

// ---------------- conversion prepasses ----------------
__global__ __launch_bounds__(256)
void convert_A_kernel(const float* __restrict__ q, const float* __restrict__ k,
                      const float* __restrict__ v)
{
    const int which = blockIdx.y;
    const float* src = (which == 0) ? q : (which == 1) ? k : v;
    __half* hi = gAh + (size_t)which * 33554432;

    size_t i4 = (size_t)blockIdx.x * blockDim.x + threadIdx.x;   // 0..8388607
    float4 x = reinterpret_cast<const float4*>(src)[i4];

    __half2 uh0 = __halves2half2(__float2half_rn(x.x), __float2half_rn(x.y));
    __half2 uh1 = __halves2half2(__float2half_rn(x.z), __float2half_rn(x.w));
    uint2 uh;
    uh.x = *reinterpret_cast<unsigned*>(&uh0);
    uh.y = *reinterpret_cast<unsigned*>(&uh1);
    reinterpret_cast<uint2*>(hi)[i4] = uh;
}

__global__ __launch_bounds__(256)
void convert_W_kernel(const float* __restrict__ wq, const float* __restrict__ wk,
                      const float* __restrict__ wv)
{
    const int which = blockIdx.z;
    const float* W = (which == 0) ? wq : (which == 1) ? wk : wv;
    __half* hi = gWt + (size_t)which * 1048576;

    __shared__ float tile[32][33];
    const int bx = blockIdx.x * 32;   // n block
    const int by = blockIdx.y * 32;   // k block
    const int tx = threadIdx.x & 31;
    const int ty = threadIdx.x >> 5;  // 0..7

#pragma unroll
    for (int i = 0; i < 32; i += 8)
        tile[ty + i][tx] = W[(size_t)(by + ty + i) * 1024 + bx + tx];
    __syncthreads();
#pragma unroll
    for (int i = 0; i < 32; i += 8) {
        float x = tile[tx][ty + i];                 // = W[by+tx][bx+ty+i]
        size_t o = (size_t)(bx + ty + i) * 1024 + by + tx;   // Wt[n][k]
        hi[o] = __float2half_rn(x);
    }
}

// ---------------- HMMA GEMM: C[M,N] = A @ W  (fp16, 3-stage, occ 2) ----------
// Tile 128x128xK64, 8 warps (2m x 4n, 64x32 warp tiles), 3-stage cp.async.
// smem/stage: A 16K | B 16K = 32K; three stages = 96K -> 2 CTAs/SM.
static constexpr int STAGE = 32768;
static constexpr int NCH = 16;        // 1024 / 64

__global__ __launch_bounds__(256, 2)
void gemm_mma_kernel()
{
    extern __shared__ char smem[];
    const int which = blockIdx.z;
    const int n0 = blockIdx.x * 128;
    const int m0 = blockIdx.y * 128;
    const int tid = threadIdx.x;
    const int wid = tid >> 5, lane = tid & 31;

    const uint32_t tiles = (smem_u32(smem) + 1023) & ~1023u;

    const __half* Ah = gAh + (size_t)which * 33554432;
    const __half* Bp = gWt + (size_t)which * 1048576;

    const int mbase_w = (wid & 1) * 64;
    const int nbase_w = (wid >> 1) * 32;

    float acc[4][4][4];
#pragma unroll
    for (int i = 0; i < 4; i++)
#pragma unroll
        for (int j = 0; j < 4; j++)
#pragma unroll
            for (int q = 0; q < 4; q++) acc[i][j][q] = 0.f;

    auto load_chunk = [&](int buf, int c) {
        const uint32_t base = tiles + buf * STAGE;
        const int k0 = c * 64;
#pragma unroll
        for (int i = tid; i < 1024; i += 256) {         // A: 128 rows x 8 chunks
            int r = i >> 3, c8 = i & 7;
            size_t gb = ((size_t)(m0 + r) * 1024 + k0 + c8 * 8) * 2;
            uint32_t d = SZ128((uint32_t)(r * 128 + c8 * 16));
            cp16(base + d, (const char*)Ah + gb);
        }
#pragma unroll
        for (int i = tid; i < 1024; i += 256) {         // B: 128 rows x 8 chunks
            int r = i >> 3, c8 = i & 7;
            size_t gb = ((size_t)(n0 + r) * 1024 + k0 + c8 * 8) * 2;
            uint32_t d = SZ128((uint32_t)(r * 128 + c8 * 16));
            cp16(base + 16384 + d, (const char*)Bp + gb);
        }
        cp_commit();
    };

    load_chunk(0, 0);
    load_chunk(1, 1);

    // lane-invariant pieces of ldmatrix addressing
    const int arow = (lane & 7) + ((lane >> 3) & 1) * 8;
    const int aoff = ((lane >> 4) & 1) * 16;
    const int brow = (lane & 7) + ((lane >> 4) & 1) * 8;
    const int boff = ((lane >> 3) & 1) * 16;

    int buf = 0;
    for (int c = 0; c < NCH; ++c) {
        if (c < NCH - 1) cp_wait<1>(); else cp_wait<0>();
        __syncthreads();
        if (c + 2 < NCH) load_chunk((buf + 2) % 3, c + 2);

        const uint32_t ab = tiles + buf * STAGE;
        const uint32_t bb = ab + 16384;

#pragma unroll
        for (int s = 0; s < 4; ++s) {
            uint32_t ah[4][4], bh2[4][2];
#pragma unroll
            for (int bg = 0; bg < 2; ++bg) {
                uint32_t u = SZ128((uint32_t)((nbase_w + bg * 16 + brow) * 128 + s * 32 + boff));
                uint32_t r[4];
                ldm4(r, bb + u);
                bh2[2 * bg][0] = r[0]; bh2[2 * bg][1] = r[1];
                bh2[2 * bg + 1][0] = r[2]; bh2[2 * bg + 1][1] = r[3];
            }
#pragma unroll
            for (int mf = 0; mf < 4; ++mf) {
                uint32_t u = SZ128((uint32_t)((mbase_w + mf * 16 + arow) * 128 + s * 32 + aoff));
                ldm4(ah[mf], ab + u);
            }
#pragma unroll
            for (int mf = 0; mf < 4; ++mf)
#pragma unroll
                for (int nf = 0; nf < 4; ++nf)
                    mma16816(acc[mf][nf], ah[mf], bh2[nf]);
        }
        buf = (buf + 1) % 3;
    }

    // epilogue: Q -> fp32; K,V -> fp16
    const int lrow = lane >> 2;
    const int lcol = (lane & 3) * 2;
    if (which == 0) {
#pragma unroll
        for (int mf = 0; mf < 4; ++mf)
#pragma unroll
            for (int nf = 0; nf < 4; ++nf) {
                int rm = m0 + mbase_w + mf * 16 + lrow;
                int cn = n0 + nbase_w + nf * 8 + lcol;
                *reinterpret_cast<float2*>(gQ + (size_t)rm * 1024 + cn) =
                    make_float2(acc[mf][nf][0], acc[mf][nf][1]);
                *reinterpret_cast<float2*>(gQ + (size_t)(rm + 8) * 1024 + cn) =
                    make_float2(acc[mf][nf][2], acc[mf][nf][3]);
            }
    } else {
        __half* Ch = (which == 1) ? gKh : gVh;
#pragma unroll
        for (int mf = 0; mf < 4; ++mf)
#pragma unroll
            for (int nf = 0; nf < 4; ++nf) {
                int rm = m0 + mbase_w + mf * 16 + lrow;
                int cn = n0 + nbase_w + nf * 8 + lcol;
                *reinterpret_cast<__half2*>(Ch + (size_t)rm * 1024 + cn) =
                    __floats2half2_rn(acc[mf][nf][0], acc[mf][nf][1]);
                *reinterpret_cast<__half2*>(Ch + (size_t)(rm + 8) * 1024 + cn) =
                    __floats2half2_rn(acc[mf][nf][2], acc[mf][nf][3]);
            }
    }
}

// ---------------- p_attn partials: LN(K)^T LN(V), HMMA consumer --------------
__global__ __launch_bounds__(256)
void pattn_partial_kernel(const float* __restrict__ lnk_s, const float* __restrict__ lnk_b,
                          const float* __restrict__ lnv_s, const float* __restrict__ lnv_b)
{
    const int bh = blockIdx.x;
    const int chunk = blockIdx.y;
    const int b = bh >> 4, h = bh & 15;
    const int n0 = chunk * ROWS_PER_CHUNK;
    const long base = (long)b * (Ss * Ff) + (long)h * (512 * 1024);

    __shared__ __half ksh[16][72];
    __shared__ __half vsh[16][72];
    __shared__ float sks[64], skb[64], svs[64], svb[64];

    const int t = threadIdx.x;
    const int warp = t >> 5, lane = t & 31;

    if (t < 64) {
        sks[t] = lnk_s[h * 64 + t];
        skb[t] = lnk_b[h * 64 + t];
        svs[t] = lnv_s[h * 64 + t];
        svb[t] = lnv_b[h * 64 + t];
    }

    const int d0 = (warp >> 1) * 16;
    const int e0 = (warp & 1) * 32;

    const uint32_t aaddr = smem_u32(
        &ksh[(lane & 7) + ((lane >> 4) & 1) * 8][d0 + ((lane >> 3) & 1) * 8]);
    const uint32_t baddr0 = smem_u32(
        &vsh[(lane & 7) + ((lane >> 3) & 1) * 8][e0 + ((lane >> 4) & 1) * 8]);
    const uint32_t baddr1 = baddr0 + 16 * 2;

    float acc[4][4];
#pragma unroll
    for (int i = 0; i < 4; i++)
#pragma unroll
        for (int j = 0; j < 4; j++) acc[i][j] = 0.f;

    for (int r0 = 0; r0 < ROWS_PER_CHUNK; r0 += 16) {
        __syncthreads();
#pragma unroll
        for (int rr = 0; rr < 2; rr++) {
            int r = 2 * warp + rr;
            long off = base + (long)(n0 + r0 + r) * 64;

            __half2 kk = reinterpret_cast<const __half2*>(gKh + off)[lane];
            __half2 vv = reinterpret_cast<const __half2*>(gVh + off)[lane];
            float2 kf = __half22float2(kk);
            float2 vf = __half22float2(vv);

            float ksum = kf.x + kf.y, ksq = kf.x * kf.x + kf.y * kf.y;
            float vsum = vf.x + vf.y, vsq = vf.x * vf.x + vf.y * vf.y;
#pragma unroll
            for (int o = 16; o > 0; o >>= 1) {
                ksum += __shfl_xor_sync(0xffffffffu, ksum, o);
                ksq  += __shfl_xor_sync(0xffffffffu, ksq, o);
                vsum += __shfl_xor_sync(0xffffffffu, vsum, o);
                vsq  += __shfl_xor_sync(0xffffffffu, vsq, o);
            }
            float kmu = ksum * (1.f / 64.f);
            float kvar = ksq * (1.f / 64.f) - kmu * kmu;
            float krs = rsqrtf(kvar + 1e-6f);
            float vmu = vsum * (1.f / 64.f);
            float vvar = vsq * (1.f / 64.f) - vmu * vmu;
            float vrs = rsqrtf(vvar + 1e-6f);

            float nk0 = (kf.x - kmu) * krs * sks[2 * lane]     + skb[2 * lane];
            float nk1 = (kf.y - kmu) * krs * sks[2 * lane + 1] + skb[2 * lane + 1];
            float nv0 = (vf.x - vmu) * vrs * svs[2 * lane]     + svb[2 * lane];
            float nv1 = (vf.y - vmu) * vrs * svs[2 * lane + 1] + svb[2 * lane + 1];

            *reinterpret_cast<__half2*>(&ksh[r][2 * lane]) = __floats2half2_rn(nk0, nk1);
            *reinterpret_cast<__half2*>(&vsh[r][2 * lane]) = __floats2half2_rn(nv0, nv1);
        }
        __syncthreads();

        uint32_t a[4], bq0[4], bq1[4];
        ldm4t(a, aaddr);
        ldm4t(bq0, baddr0);
        ldm4t(bq1, baddr1);
        uint32_t bfr[4][2] = {{bq0[0], bq0[1]}, {bq0[2], bq0[3]},
                              {bq1[0], bq1[1]}, {bq1[2], bq1[3]}};
#pragma unroll
        for (int nf = 0; nf < 4; ++nf)
            mma16816(acc[nf], a, bfr[nf]);
    }

    float* p = gPpart + ((long)chunk * 64 + bh) * 4096;
    const int lrow = lane >> 2;
    const int lcol = (lane & 3) * 2;
#pragma unroll
    for (int nf = 0; nf < 4; ++nf) {
        int e = e0 + nf * 8 + lcol;
        *reinterpret_cast<float2*>(p + (d0 + lrow) * 64 + e) =
            make_float2(acc[nf][0], acc[nf][1]);
        *reinterpret_cast<float2*>(p + (d0 + lrow + 8) * 64 + e) =
            make_float2(acc[nf][2], acc[nf][3]);
    }
}

__global__ void pattn_reduce_kernel(float* __restrict__ pout)
{
    int i = blockIdx.x * blockDim.x + threadIdx.x;
    if (i >= 64 * 4096) return;
    int bh = i >> 12;
    int idx = i & 4095;
    float s = 0.f;
#pragma unroll
    for (int c = 0; c < NCHUNK; c++)
        s += gPpart[((long)c * 64 + bh) * 4096 + idx];
    pout[i] = s * (1.f / 8192.f);
}

__global__ __launch_bounds__(256)
void out_kernel(const float* __restrict__ pattn, float* __restrict__ out)
{
    const int bh = blockIdx.y;
    const int b = bh >> 4, h = bh & 15;
    const int n0 = blockIdx.x * 64;

    __shared__ float ps[64][64];
    __shared__ float qs[64][68];

    const int t = threadIdx.x;
    const float* P = pattn + (long)bh * 4096;
    for (int i = t; i < 4096; i += 256)
        ps[i >> 6][i & 63] = P[i];

    const long base = (long)b * (Ss * Ff) + (long)h * 524288 + (long)n0 * 64;
#pragma unroll
    for (int it = 0; it < 4; it++) {
        int i = t * 4 + it * 1024;
        *(float4*)(&qs[i >> 6][i & 63]) = *(const float4*)(gQ + base + i);
    }
    __syncthreads();

    const int r  = t >> 2;
    const int eg = (t & 3) * 16;

    float acc[16];
#pragma unroll
    for (int j = 0; j < 16; j++) acc[j] = 0.f;

#pragma unroll
    for (int d = 0; d < 64; d++) {
        float q = qs[r][d];
#pragma unroll
        for (int j4 = 0; j4 < 4; j4++) {
            float4 pv = *(const float4*)(&ps[d][eg + j4 * 4]);
            acc[j4 * 4 + 0] += q * pv.x;
            acc[j4 * 4 + 1] += q * pv.y;
            acc[j4 * 4 + 2] += q * pv.z;
            acc[j4 * 4 + 3] += q * pv.w;
        }
    }

    float* o = out + base + (long)r * 64 + eg;
#pragma unroll
    for (int j4 = 0; j4 < 4; j4++)
        *(float4*)(o + j4 * 4) = make_float4(acc[j4 * 4 + 0], acc[j4 * 4 + 1],
                                             acc[j4 * 4 + 2], acc[j4 * 4 + 3]);
}

// ---------------- launch ----------------------------------------------------
extern "C" void kernel_launch(void* const* d_in, const int* in_sizes, int n_in,
                              void* d_out, int out_size)
{
    (void)in_sizes; (void)n_in; (void)out_size;
    const float* query = (const float*)d_in[0];
    const float* key   = (const float*)d_in[1];
    const float* value = (const float*)d_in[2];
    const float* Wq    = (const float*)d_in[3];
    const float* Wk    = (const float*)d_in[4];
    const float* Wv    = (const float*)d_in[5];
    const float* lnk_s = (const float*)d_in[6];
    const float* lnk_b = (const float*)d_in[7];
    const float* lnv_s = (const float*)d_in[8];
    const float* lnv_b = (const float*)d_in[9];

    float* out = (float*)d_out;
    float* pout = out + QELEMS;

    cudaFuncSetAttribute(gemm_mma_kernel, cudaFuncAttributeMaxDynamicSharedMemorySize,
                         3 * STAGE + 1024);

    convert_A_kernel<<<dim3(32768, 3), 256>>>(query, key, value);
    convert_W_kernel<<<dim3(32, 32, 3), 256>>>(Wq, Wk, Wv);

    gemm_mma_kernel<<<dim3(8, 256, 3), 256, 3 * STAGE + 1024>>>();

    dim3 pgrid(64, NCHUNK);
    pattn_partial_kernel<<<pgrid, 256>>>(lnk_s, lnk_b, lnv_s, lnv_b);
    pattn_reduce_kernel<<<(64 * 4096 + 255) / 256, 256>>>(pout);

    dim3 ogrid(8192 / 64, 64);
    out_kernel<<<ogrid, 256>>>(pout, out);
}

// round 11
// speedup vs baseline: 4.1947x; 1.0146x over previous
#include <cuda_runtime.h>
#include <cuda_fp16.h>
#include <cstdint>

// ---------------- problem constants ----------------
static constexpr int Bb = 4, Ss = 8192, Ff = 1024, Hh = 16, Dd = 64;
static constexpr int Mm = Bb * Ss;              // 32768
static constexpr int Kk = 1024, Nn = 1024;
static constexpr long QELEMS = (long)Mm * Ff;   // 33554432
static constexpr int NCHUNK = 32;
static constexpr int ROWS_PER_CHUNK = 8192 / NCHUNK;  // 256

// ---------------- scratch (device globals) ----------------
__device__ __half gQh[33554432];                // Q projection, fp16
__device__ __half gKh[33554432];                // K projection, fp16
__device__ __half gVh[33554432];                // V projection, fp16
__device__ float gPpart[(long)NCHUNK * 64 * 4096];
__device__ __half gAh[3L * 33554432];
__device__ __half gWt[3L * 1048576];            // W^T: [n][k], k contiguous, fp16

// ---------------- helpers ----------------
__device__ __forceinline__ uint32_t smem_u32(const void* p) {
    uint32_t a;
    asm("{ .reg .u64 t; cvta.to.shared.u64 t, %1; cvt.u32.u64 %0, t; }" : "=r"(a) : "l"(p));
    return a;
}
// Swizzle<3,4,3> for 128B rows: XOR 16B-chunk bits [4:6] with row bits [7:9]
__device__ __forceinline__ uint32_t SZ128(uint32_t a) { return a ^ ((a >> 3) & 0x70u); }

__device__ __forceinline__ void cp16(uint32_t dst, const void* src) {
    asm volatile("cp.async.cg.shared.global [%0], [%1], 16;\n" :: "r"(dst), "l"(src));
}
__device__ __forceinline__ void cp_commit() { asm volatile("cp.async.commit_group;\n"); }
template<int N> __device__ __forceinline__ void cp_wait() {
    asm volatile("cp.async.wait_group %0;\n" :: "n"(N));
}
__device__ __forceinline__ void ldm4(uint32_t* r, uint32_t addr) {
    asm volatile("ldmatrix.sync.aligned.m8n8.x4.shared.b16 {%0,%1,%2,%3}, [%4];"
                 : "=r"(r[0]), "=r"(r[1]), "=r"(r[2]), "=r"(r[3]) : "r"(addr));
}
__device__ __forceinline__ void ldm4t(uint32_t* r, uint32_t addr) {
    asm volatile("ldmatrix.sync.aligned.m8n8.x4.trans.shared.b16 {%0,%1,%2,%3}, [%4];"
                 : "=r"(r[0]), "=r"(r[1]), "=r"(r[2]), "=r"(r[3]) : "r"(addr));
}
__device__ __forceinline__ void mma16816(float* d, const uint32_t* a, const uint32_t* b) {
    asm volatile(
        "mma.sync.aligned.m16n8k16.row.col.f32.f16.f16.f32 "
        "{%0,%1,%2,%3}, {%4,%5,%6,%7}, {%8,%9}, {%0,%1,%2,%3};"
        : "+f"(d[0]), "+f"(d[1]), "+f"(d[2]), "+f"(d[3])
        : "r"(a[0]), "r"(a[1]), "r"(a[2]), "r"(a[3]), "r"(b[0]), "r"(b[1]));
}

// ---------------- conversion prepasses ----------------
__global__ __launch_bounds__(256)
void convert_A_kernel(const float* __restrict__ q, const float* __restrict__ k,
                      const float* __restrict__ v)
{
    const int which = blockIdx.y;
    const float* src = (which == 0) ? q : (which == 1) ? k : v;
    __half* hi = gAh + (size_t)which * 33554432;

    size_t i8 = (size_t)blockIdx.x * blockDim.x + threadIdx.x;   // 0..4194303
    float4 x0 = reinterpret_cast<const float4*>(src)[2 * i8];
    float4 x1 = reinterpret_cast<const float4*>(src)[2 * i8 + 1];

    __half2 a0 = __halves2half2(__float2half_rn(x0.x), __float2half_rn(x0.y));
    __half2 a1 = __halves2half2(__float2half_rn(x0.z), __float2half_rn(x0.w));
    __half2 a2 = __halves2half2(__float2half_rn(x1.x), __float2half_rn(x1.y));
    __half2 a3 = __halves2half2(__float2half_rn(x1.z), __float2half_rn(x1.w));
    uint4 u;
    u.x = *reinterpret_cast<unsigned*>(&a0);
    u.y = *reinterpret_cast<unsigned*>(&a1);
    u.z = *reinterpret_cast<unsigned*>(&a2);
    u.w = *reinterpret_cast<unsigned*>(&a3);
    reinterpret_cast<uint4*>(hi)[i8] = u;
}

__global__ __launch_bounds__(256)
void convert_W_kernel(const float* __restrict__ wq, const float* __restrict__ wk,
                      const float* __restrict__ wv)
{
    const int which = blockIdx.z;
    const float* W = (which == 0) ? wq : (which == 1) ? wk : wv;
    __half* hi = gWt + (size_t)which * 1048576;

    __shared__ float tile[32][33];
    const int bx = blockIdx.x * 32;   // n block
    const int by = blockIdx.y * 32;   // k block
    const int tx = threadIdx.x & 31;
    const int ty = threadIdx.x >> 5;  // 0..7

#pragma unroll
    for (int i = 0; i < 32; i += 8)
        tile[ty + i][tx] = W[(size_t)(by + ty + i) * 1024 + bx + tx];
    __syncthreads();
#pragma unroll
    for (int i = 0; i < 32; i += 8) {
        float x = tile[tx][ty + i];                 // = W[by+tx][bx+ty+i]
        size_t o = (size_t)(bx + ty + i) * 1024 + by + tx;   // Wt[n][k]
        hi[o] = __float2half_rn(x);
    }
}

// ---------------- HMMA GEMM: C[M,N] = A @ W  (fp16, 3-stage, occ 2) ----------
// Tile 128x128xK64, 8 warps (2m x 4n, 64x32 warp tiles), 3-stage cp.async.
static constexpr int STAGE = 32768;
static constexpr int NCH = 16;        // 1024 / 64

__global__ __launch_bounds__(256, 2)
void gemm_mma_kernel()
{
    extern __shared__ char smem[];
    const int which = blockIdx.z;
    const int n0 = blockIdx.x * 128;
    const int m0 = blockIdx.y * 128;
    const int tid = threadIdx.x;
    const int wid = tid >> 5, lane = tid & 31;

    const uint32_t tiles = (smem_u32(smem) + 1023) & ~1023u;

    const __half* Ah = gAh + (size_t)which * 33554432;
    const __half* Bp = gWt + (size_t)which * 1048576;

    const int mbase_w = (wid & 1) * 64;
    const int nbase_w = (wid >> 1) * 32;

    float acc[4][4][4];
#pragma unroll
    for (int i = 0; i < 4; i++)
#pragma unroll
        for (int j = 0; j < 4; j++)
#pragma unroll
            for (int q = 0; q < 4; q++) acc[i][j][q] = 0.f;

    auto load_chunk = [&](int buf, int c) {
        const uint32_t base = tiles + buf * STAGE;
        const int k0 = c * 64;
#pragma unroll
        for (int i = tid; i < 1024; i += 256) {         // A: 128 rows x 8 chunks
            int r = i >> 3, c8 = i & 7;
            size_t gb = ((size_t)(m0 + r) * 1024 + k0 + c8 * 8) * 2;
            uint32_t d = SZ128((uint32_t)(r * 128 + c8 * 16));
            cp16(base + d, (const char*)Ah + gb);
        }
#pragma unroll
        for (int i = tid; i < 1024; i += 256) {         // B: 128 rows x 8 chunks
            int r = i >> 3, c8 = i & 7;
            size_t gb = ((size_t)(n0 + r) * 1024 + k0 + c8 * 8) * 2;
            uint32_t d = SZ128((uint32_t)(r * 128 + c8 * 16));
            cp16(base + 16384 + d, (const char*)Bp + gb);
        }
        cp_commit();
    };

    load_chunk(0, 0);
    load_chunk(1, 1);

    const int arow = (lane & 7) + ((lane >> 3) & 1) * 8;
    const int aoff = ((lane >> 4) & 1) * 16;
    const int brow = (lane & 7) + ((lane >> 4) & 1) * 8;
    const int boff = ((lane >> 3) & 1) * 16;

    int buf = 0;
    for (int c = 0; c < NCH; ++c) {
        if (c < NCH - 1) cp_wait<1>(); else cp_wait<0>();
        __syncthreads();
        if (c + 2 < NCH) load_chunk((buf + 2) % 3, c + 2);

        const uint32_t ab = tiles + buf * STAGE;
        const uint32_t bb = ab + 16384;

#pragma unroll
        for (int s = 0; s < 4; ++s) {
            uint32_t ah[4][4], bh2[4][2];
#pragma unroll
            for (int bg = 0; bg < 2; ++bg) {
                uint32_t u = SZ128((uint32_t)((nbase_w + bg * 16 + brow) * 128 + s * 32 + boff));
                uint32_t r[4];
                ldm4(r, bb + u);
                bh2[2 * bg][0] = r[0]; bh2[2 * bg][1] = r[1];
                bh2[2 * bg + 1][0] = r[2]; bh2[2 * bg + 1][1] = r[3];
            }
#pragma unroll
            for (int mf = 0; mf < 4; ++mf) {
                uint32_t u = SZ128((uint32_t)((mbase_w + mf * 16 + arow) * 128 + s * 32 + aoff));
                ldm4(ah[mf], ab + u);
            }
#pragma unroll
            for (int mf = 0; mf < 4; ++mf)
#pragma unroll
                for (int nf = 0; nf < 4; ++nf)
                    mma16816(acc[mf][nf], ah[mf], bh2[nf]);
        }
        buf = (buf + 1) % 3;
    }

    // epilogue: all projections stored fp16
    __half* Ch = (which == 0) ? gQh : (which == 1) ? gKh : gVh;
    const int lrow = lane >> 2;
    const int lcol = (lane & 3) * 2;
#pragma unroll
    for (int mf = 0; mf < 4; ++mf)
#pragma unroll
        for (int nf = 0; nf < 4; ++nf) {
            int rm = m0 + mbase_w + mf * 16 + lrow;
            int cn = n0 + nbase_w + nf * 8 + lcol;
            *reinterpret_cast<__half2*>(Ch + (size_t)rm * 1024 + cn) =
                __floats2half2_rn(acc[mf][nf][0], acc[mf][nf][1]);
            *reinterpret_cast<__half2*>(Ch + (size_t)(rm + 8) * 1024 + cn) =
                __floats2half2_rn(acc[mf][nf][2], acc[mf][nf][3]);
        }
}

// ---------------- p_attn partials: LN(K)^T LN(V), HMMA consumer --------------
__global__ __launch_bounds__(256)
void pattn_partial_kernel(const float* __restrict__ lnk_s, const float* __restrict__ lnk_b,
                          const float* __restrict__ lnv_s, const float* __restrict__ lnv_b)
{
    const int bh = blockIdx.x;
    const int chunk = blockIdx.y;
    const int b = bh >> 4, h = bh & 15;
    const int n0 = chunk * ROWS_PER_CHUNK;
    const long base = (long)b * (Ss * Ff) + (long)h * (512 * 1024);

    __shared__ __half ksh[16][72];
    __shared__ __half vsh[16][72];
    __shared__ float sks[64], skb[64], svs[64], svb[64];

    const int t = threadIdx.x;
    const int warp = t >> 5, lane = t & 31;

    if (t < 64) {
        sks[t] = lnk_s[h * 64 + t];
        skb[t] = lnk_b[h * 64 + t];
        svs[t] = lnv_s[h * 64 + t];
        svb[t] = lnv_b[h * 64 + t];
    }

    const int d0 = (warp >> 1) * 16;
    const int e0 = (warp & 1) * 32;

    const uint32_t aaddr = smem_u32(
        &ksh[(lane & 7) + ((lane >> 4) & 1) * 8][d0 + ((lane >> 3) & 1) * 8]);
    const uint32_t baddr0 = smem_u32(
        &vsh[(lane & 7) + ((lane >> 3) & 1) * 8][e0 + ((lane >> 4) & 1) * 8]);
    const uint32_t baddr1 = baddr0 + 16 * 2;

    float acc[4][4];
#pragma unroll
    for (int i = 0; i < 4; i++)
#pragma unroll
        for (int j = 0; j < 4; j++) acc[i][j] = 0.f;

    for (int r0 = 0; r0 < ROWS_PER_CHUNK; r0 += 16) {
        __syncthreads();
#pragma unroll
        for (int rr = 0; rr < 2; rr++) {
            int r = 2 * warp + rr;
            long off = base + (long)(n0 + r0 + r) * 64;

            __half2 kk = reinterpret_cast<const __half2*>(gKh + off)[lane];
            __half2 vv = reinterpret_cast<const __half2*>(gVh + off)[lane];
            float2 kf = __half22float2(kk);
            float2 vf = __half22float2(vv);

            float ksum = kf.x + kf.y, ksq = kf.x * kf.x + kf.y * kf.y;
            float vsum = vf.x + vf.y, vsq = vf.x * vf.x + vf.y * vf.y;
#pragma unroll
            for (int o = 16; o > 0; o >>= 1) {
                ksum += __shfl_xor_sync(0xffffffffu, ksum, o);
                ksq  += __shfl_xor_sync(0xffffffffu, ksq, o);
                vsum += __shfl_xor_sync(0xffffffffu, vsum, o);
                vsq  += __shfl_xor_sync(0xffffffffu, vsq, o);
            }
            float kmu = ksum * (1.f / 64.f);
            float kvar = ksq * (1.f / 64.f) - kmu * kmu;
            float krs = rsqrtf(kvar + 1e-6f);
            float vmu = vsum * (1.f / 64.f);
            float vvar = vsq * (1.f / 64.f) - vmu * vmu;
            float vrs = rsqrtf(vvar + 1e-6f);

            float nk0 = (kf.x - kmu) * krs * sks[2 * lane]     + skb[2 * lane];
            float nk1 = (kf.y - kmu) * krs * sks[2 * lane + 1] + skb[2 * lane + 1];
            float nv0 = (vf.x - vmu) * vrs * svs[2 * lane]     + svb[2 * lane];
            float nv1 = (vf.y - vmu) * vrs * svs[2 * lane + 1] + svb[2 * lane + 1];

            *reinterpret_cast<__half2*>(&ksh[r][2 * lane]) = __floats2half2_rn(nk0, nk1);
            *reinterpret_cast<__half2*>(&vsh[r][2 * lane]) = __floats2half2_rn(nv0, nv1);
        }
        __syncthreads();

        uint32_t a[4], bq0[4], bq1[4];
        ldm4t(a, aaddr);
        ldm4t(bq0, baddr0);
        ldm4t(bq1, baddr1);
        uint32_t bfr[4][2] = {{bq0[0], bq0[1]}, {bq0[2], bq0[3]},
                              {bq1[0], bq1[1]}, {bq1[2], bq1[3]}};
#pragma unroll
        for (int nf = 0; nf < 4; ++nf)
            mma16816(acc[nf], a, bfr[nf]);
    }

    float* p = gPpart + ((long)chunk * 64 + bh) * 4096;
    const int lrow = lane >> 2;
    const int lcol = (lane & 3) * 2;
#pragma unroll
    for (int nf = 0; nf < 4; ++nf) {
        int e = e0 + nf * 8 + lcol;
        *reinterpret_cast<float2*>(p + (d0 + lrow) * 64 + e) =
            make_float2(acc[nf][0], acc[nf][1]);
        *reinterpret_cast<float2*>(p + (d0 + lrow + 8) * 64 + e) =
            make_float2(acc[nf][2], acc[nf][3]);
    }
}

__global__ void pattn_reduce_kernel(float* __restrict__ pout)
{
    int i = blockIdx.x * blockDim.x + threadIdx.x;
    if (i >= 64 * 4096) return;
    int bh = i >> 12;
    int idx = i & 4095;
    float s = 0.f;
#pragma unroll
    for (int c = 0; c < NCHUNK; c++)
        s += gPpart[((long)c * 64 + bh) * 4096 + idx];
    pout[i] = s * (1.f / 8192.f);
}

// ---------------- x = Q @ P per (b,h): scalar FFMA, fp16 Q, fp32 P -----------
__global__ __launch_bounds__(256)
void out_kernel(const float* __restrict__ pattn, float* __restrict__ out)
{
    const int bh = blockIdx.y;
    const int b = bh >> 4, h = bh & 15;
    const int n0 = blockIdx.x * 64;

    __shared__ float ps[64][64];
    __shared__ float qs[64][68];

    const int t = threadIdx.x;
    const float* P = pattn + (long)bh * 4096;
    for (int i = t; i < 4096; i += 256)
        ps[i >> 6][i & 63] = P[i];

    const size_t base = (size_t)b * (Ss * Ff) + (size_t)h * 524288 + (size_t)n0 * 64;
#pragma unroll
    for (int it = 0; it < 4; it++) {
        int i = t * 4 + it * 1024;          // element index, multiple of 4
        uint2 qu = *reinterpret_cast<const uint2*>(gQh + base + i);
        float2 f01 = __half22float2(*reinterpret_cast<__half2*>(&qu.x));
        float2 f23 = __half22float2(*reinterpret_cast<__half2*>(&qu.y));
        *reinterpret_cast<float4*>(&qs[i >> 6][i & 63]) =
            make_float4(f01.x, f01.y, f23.x, f23.y);
    }
    __syncthreads();

    const int r  = t >> 2;
    const int eg = (t & 3) * 16;

    float acc[16];
#pragma unroll
    for (int j = 0; j < 16; j++) acc[j] = 0.f;

#pragma unroll
    for (int d = 0; d < 64; d++) {
        float q = qs[r][d];
#pragma unroll
        for (int j4 = 0; j4 < 4; j4++) {
            float4 pv = *reinterpret_cast<const float4*>(&ps[d][eg + j4 * 4]);
            acc[j4 * 4 + 0] += q * pv.x;
            acc[j4 * 4 + 1] += q * pv.y;
            acc[j4 * 4 + 2] += q * pv.z;
            acc[j4 * 4 + 3] += q * pv.w;
        }
    }

    float* o = out + base + (size_t)r * 64 + eg;
#pragma unroll
    for (int j4 = 0; j4 < 4; j4++)
        *reinterpret_cast<float4*>(o + j4 * 4) =
            make_float4(acc[j4 * 4 + 0], acc[j4 * 4 + 1],
                        acc[j4 * 4 + 2], acc[j4 * 4 + 3]);
}

// ---------------- launch ----------------------------------------------------
extern "C" void kernel_launch(void* const* d_in, const int* in_sizes, int n_in,
                              void* d_out, int out_size)
{
    (void)in_sizes; (void)n_in; (void)out_size;
    const float* query = (const float*)d_in[0];
    const float* key   = (const float*)d_in[1];
    const float* value = (const float*)d_in[2];
    const float* Wq    = (const float*)d_in[3];
    const float* Wk    = (const float*)d_in[4];
    const float* Wv    = (const float*)d_in[5];
    const float* lnk_s = (const float*)d_in[6];
    const float* lnk_b = (const float*)d_in[7];
    const float* lnv_s = (const float*)d_in[8];
    const float* lnv_b = (const float*)d_in[9];

    float* out = (float*)d_out;
    float* pout = out + QELEMS;

    cudaFuncSetAttribute(gemm_mma_kernel, cudaFuncAttributeMaxDynamicSharedMemorySize,
                         3 * STAGE + 1024);

    convert_A_kernel<<<dim3(16384, 3), 256>>>(query, key, value);
    convert_W_kernel<<<dim3(32, 32, 3), 256>>>(Wq, Wk, Wv);

    gemm_mma_kernel<<<dim3(8, 256, 3), 256, 3 * STAGE + 1024>>>();

    dim3 pgrid(64, NCHUNK);
    pattn_partial_kernel<<<pgrid, 256>>>(lnk_s, lnk_b, lnv_s, lnv_b);
    pattn_reduce_kernel<<<(64 * 4096 + 255) / 256, 256>>>(pout);

    dim3 ogrid(8192 / 64, 64);
    out_kernel<<<ogrid, 256>>>(pout, out);
}

// round 12
// speedup vs baseline: 6.5452x; 1.5603x over previous
#include <cuda_runtime.h>
#include <cuda_fp16.h>
#include <cstdint>

// ---------------- problem constants ----------------
static constexpr int Bb = 4, Ss = 8192, Ff = 1024, Hh = 16, Dd = 64;
static constexpr int Mm = Bb * Ss;              // 32768
static constexpr int Kk = 1024, Nn = 1024;
static constexpr long QELEMS = (long)Mm * Ff;   // 33554432
static constexpr int NCHUNK = 32;
static constexpr int ROWS_PER_CHUNK = 8192 / NCHUNK;  // 256

// ---------------- scratch (device globals) ----------------
__device__ __half gQh[33554432];                // Q projection, fp16
__device__ __half gKh[33554432];                // K projection, fp16
__device__ __half gVh[33554432];                // V projection, fp16
__device__ float gPpart[(long)NCHUNK * 64 * 4096];
__device__ __half gPh[64 * 4096];               // fp16 copy of p_attn for out HMMA
__device__ __half gAh[3L * 33554432];
__device__ __half gWt[3L * 1048576];            // W^T: [n][k], k contiguous, fp16

// ---------------- helpers ----------------
__device__ __forceinline__ uint32_t smem_u32(const void* p) {
    uint32_t a;
    asm("{ .reg .u64 t; cvta.to.shared.u64 t, %1; cvt.u32.u64 %0, t; }" : "=r"(a) : "l"(p));
    return a;
}
// Swizzle<3,4,3> for 128B rows: XOR 16B-chunk bits [4:6] with row bits [7:9]
__device__ __forceinline__ uint32_t SZ128(uint32_t a) { return a ^ ((a >> 3) & 0x70u); }

__device__ __forceinline__ void cp16(uint32_t dst, const void* src) {
    asm volatile("cp.async.cg.shared.global [%0], [%1], 16;\n" :: "r"(dst), "l"(src));
}
__device__ __forceinline__ void cp_commit() { asm volatile("cp.async.commit_group;\n"); }
template<int N> __device__ __forceinline__ void cp_wait() {
    asm volatile("cp.async.wait_group %0;\n" :: "n"(N));
}
__device__ __forceinline__ void ldm4(uint32_t* r, uint32_t addr) {
    asm volatile("ldmatrix.sync.aligned.m8n8.x4.shared.b16 {%0,%1,%2,%3}, [%4];"
                 : "=r"(r[0]), "=r"(r[1]), "=r"(r[2]), "=r"(r[3]) : "r"(addr));
}
__device__ __forceinline__ void ldm4t(uint32_t* r, uint32_t addr) {
    asm volatile("ldmatrix.sync.aligned.m8n8.x4.trans.shared.b16 {%0,%1,%2,%3}, [%4];"
                 : "=r"(r[0]), "=r"(r[1]), "=r"(r[2]), "=r"(r[3]) : "r"(addr));
}
__device__ __forceinline__ void mma16816(float* d, const uint32_t* a, const uint32_t* b) {
    asm volatile(
        "mma.sync.aligned.m16n8k16.row.col.f32.f16.f16.f32 "
        "{%0,%1,%2,%3}, {%4,%5,%6,%7}, {%8,%9}, {%0,%1,%2,%3};"
        : "+f"(d[0]), "+f"(d[1]), "+f"(d[2]), "+f"(d[3])
        : "r"(a[0]), "r"(a[1]), "r"(a[2]), "r"(a[3]), "r"(b[0]), "r"(b[1]));
}

// ---------------- conversion prepasses ----------------
__global__ __launch_bounds__(256)
void convert_A_kernel(const float* __restrict__ q, const float* __restrict__ k,
                      const float* __restrict__ v)
{
    const int which = blockIdx.y;
    const float* src = (which == 0) ? q : (which == 1) ? k : v;
    __half* hi = gAh + (size_t)which * 33554432;

    size_t i8 = (size_t)blockIdx.x * blockDim.x + threadIdx.x;   // 0..4194303
    float4 x0 = reinterpret_cast<const float4*>(src)[2 * i8];
    float4 x1 = reinterpret_cast<const float4*>(src)[2 * i8 + 1];

    __half2 a0 = __halves2half2(__float2half_rn(x0.x), __float2half_rn(x0.y));
    __half2 a1 = __halves2half2(__float2half_rn(x0.z), __float2half_rn(x0.w));
    __half2 a2 = __halves2half2(__float2half_rn(x1.x), __float2half_rn(x1.y));
    __half2 a3 = __halves2half2(__float2half_rn(x1.z), __float2half_rn(x1.w));
    uint4 u;
    u.x = *reinterpret_cast<unsigned*>(&a0);
    u.y = *reinterpret_cast<unsigned*>(&a1);
    u.z = *reinterpret_cast<unsigned*>(&a2);
    u.w = *reinterpret_cast<unsigned*>(&a3);
    reinterpret_cast<uint4*>(hi)[i8] = u;
}

__global__ __launch_bounds__(256)
void convert_W_kernel(const float* __restrict__ wq, const float* __restrict__ wk,
                      const float* __restrict__ wv)
{
    const int which = blockIdx.z;
    const float* W = (which == 0) ? wq : (which == 1) ? wk : wv;
    __half* hi = gWt + (size_t)which * 1048576;

    __shared__ float tile[32][33];
    const int bx = blockIdx.x * 32;   // n block
    const int by = blockIdx.y * 32;   // k block
    const int tx = threadIdx.x & 31;
    const int ty = threadIdx.x >> 5;  // 0..7

#pragma unroll
    for (int i = 0; i < 32; i += 8)
        tile[ty + i][tx] = W[(size_t)(by + ty + i) * 1024 + bx + tx];
    __syncthreads();
#pragma unroll
    for (int i = 0; i < 32; i += 8) {
        float x = tile[tx][ty + i];                 // = W[by+tx][bx+ty+i]
        size_t o = (size_t)(bx + ty + i) * 1024 + by + tx;   // Wt[n][k]
        hi[o] = __float2half_rn(x);
    }
}

// ---------------- HMMA GEMM: C[M,N] = A @ W  (fp16, 3-stage, occ 2) ----------
// Tile 128x128xK64, 8 warps (2m x 4n, 64x32 warp tiles), 3-stage cp.async.
static constexpr int STAGE = 32768;
static constexpr int NCH = 16;        // 1024 / 64

__global__ __launch_bounds__(256, 2)
void gemm_mma_kernel()
{
    extern __shared__ char smem[];
    const int which = blockIdx.z;
    const int n0 = blockIdx.x * 128;
    const int m0 = blockIdx.y * 128;
    const int tid = threadIdx.x;
    const int wid = tid >> 5, lane = tid & 31;

    const uint32_t tiles = (smem_u32(smem) + 1023) & ~1023u;

    const __half* Ah = gAh + (size_t)which * 33554432;
    const __half* Bp = gWt + (size_t)which * 1048576;

    const int mbase_w = (wid & 1) * 64;
    const int nbase_w = (wid >> 1) * 32;

    float acc[4][4][4];
#pragma unroll
    for (int i = 0; i < 4; i++)
#pragma unroll
        for (int j = 0; j < 4; j++)
#pragma unroll
            for (int q = 0; q < 4; q++) acc[i][j][q] = 0.f;

    auto load_chunk = [&](int buf, int c) {
        const uint32_t base = tiles + buf * STAGE;
        const int k0 = c * 64;
#pragma unroll
        for (int i = tid; i < 1024; i += 256) {         // A: 128 rows x 8 chunks
            int r = i >> 3, c8 = i & 7;
            size_t gb = ((size_t)(m0 + r) * 1024 + k0 + c8 * 8) * 2;
            uint32_t d = SZ128((uint32_t)(r * 128 + c8 * 16));
            cp16(base + d, (const char*)Ah + gb);
        }
#pragma unroll
        for (int i = tid; i < 1024; i += 256) {         // B: 128 rows x 8 chunks
            int r = i >> 3, c8 = i & 7;
            size_t gb = ((size_t)(n0 + r) * 1024 + k0 + c8 * 8) * 2;
            uint32_t d = SZ128((uint32_t)(r * 128 + c8 * 16));
            cp16(base + 16384 + d, (const char*)Bp + gb);
        }
        cp_commit();
    };

    load_chunk(0, 0);
    load_chunk(1, 1);

    const int arow = (lane & 7) + ((lane >> 3) & 1) * 8;
    const int aoff = ((lane >> 4) & 1) * 16;
    const int brow = (lane & 7) + ((lane >> 4) & 1) * 8;
    const int boff = ((lane >> 3) & 1) * 16;

    int buf = 0;
    for (int c = 0; c < NCH; ++c) {
        if (c < NCH - 1) cp_wait<1>(); else cp_wait<0>();
        __syncthreads();
        if (c + 2 < NCH) load_chunk((buf + 2) % 3, c + 2);

        const uint32_t ab = tiles + buf * STAGE;
        const uint32_t bb = ab + 16384;

#pragma unroll
        for (int s = 0; s < 4; ++s) {
            uint32_t ah[4][4], bh2[4][2];
#pragma unroll
            for (int bg = 0; bg < 2; ++bg) {
                uint32_t u = SZ128((uint32_t)((nbase_w + bg * 16 + brow) * 128 + s * 32 + boff));
                uint32_t r[4];
                ldm4(r, bb + u);
                bh2[2 * bg][0] = r[0]; bh2[2 * bg][1] = r[1];
                bh2[2 * bg + 1][0] = r[2]; bh2[2 * bg + 1][1] = r[3];
            }
#pragma unroll
            for (int mf = 0; mf < 4; ++mf) {
                uint32_t u = SZ128((uint32_t)((mbase_w + mf * 16 + arow) * 128 + s * 32 + aoff));
                ldm4(ah[mf], ab + u);
            }
#pragma unroll
            for (int mf = 0; mf < 4; ++mf)
#pragma unroll
                for (int nf = 0; nf < 4; ++nf)
                    mma16816(acc[mf][nf], ah[mf], bh2[nf]);
        }
        buf = (buf + 1) % 3;
    }

    // epilogue: all projections stored fp16
    __half* Ch = (which == 0) ? gQh : (which == 1) ? gKh : gVh;
    const int lrow = lane >> 2;
    const int lcol = (lane & 3) * 2;
#pragma unroll
    for (int mf = 0; mf < 4; ++mf)
#pragma unroll
        for (int nf = 0; nf < 4; ++nf) {
            int rm = m0 + mbase_w + mf * 16 + lrow;
            int cn = n0 + nbase_w + nf * 8 + lcol;
            *reinterpret_cast<__half2*>(Ch + (size_t)rm * 1024 + cn) =
                __floats2half2_rn(acc[mf][nf][0], acc[mf][nf][1]);
            *reinterpret_cast<__half2*>(Ch + (size_t)(rm + 8) * 1024 + cn) =
                __floats2half2_rn(acc[mf][nf][2], acc[mf][nf][3]);
        }
}

// ---------------- p_attn partials: LN(K)^T LN(V), HMMA consumer --------------
__global__ __launch_bounds__(256)
void pattn_partial_kernel(const float* __restrict__ lnk_s, const float* __restrict__ lnk_b,
                          const float* __restrict__ lnv_s, const float* __restrict__ lnv_b)
{
    const int bh = blockIdx.x;
    const int chunk = blockIdx.y;
    const int b = bh >> 4, h = bh & 15;
    const int n0 = chunk * ROWS_PER_CHUNK;
    const long base = (long)b * (Ss * Ff) + (long)h * (512 * 1024);

    __shared__ __half ksh[16][72];
    __shared__ __half vsh[16][72];
    __shared__ float sks[64], skb[64], svs[64], svb[64];

    const int t = threadIdx.x;
    const int warp = t >> 5, lane = t & 31;

    if (t < 64) {
        sks[t] = lnk_s[h * 64 + t];
        skb[t] = lnk_b[h * 64 + t];
        svs[t] = lnv_s[h * 64 + t];
        svb[t] = lnv_b[h * 64 + t];
    }

    const int d0 = (warp >> 1) * 16;
    const int e0 = (warp & 1) * 32;

    const uint32_t aaddr = smem_u32(
        &ksh[(lane & 7) + ((lane >> 4) & 1) * 8][d0 + ((lane >> 3) & 1) * 8]);
    const uint32_t baddr0 = smem_u32(
        &vsh[(lane & 7) + ((lane >> 3) & 1) * 8][e0 + ((lane >> 4) & 1) * 8]);
    const uint32_t baddr1 = baddr0 + 16 * 2;

    float acc[4][4];
#pragma unroll
    for (int i = 0; i < 4; i++)
#pragma unroll
        for (int j = 0; j < 4; j++) acc[i][j] = 0.f;

    for (int r0 = 0; r0 < ROWS_PER_CHUNK; r0 += 16) {
        __syncthreads();
#pragma unroll
        for (int rr = 0; rr < 2; rr++) {
            int r = 2 * warp + rr;
            long off = base + (long)(n0 + r0 + r) * 64;

            __half2 kk = reinterpret_cast<const __half2*>(gKh + off)[lane];
            __half2 vv = reinterpret_cast<const __half2*>(gVh + off)[lane];
            float2 kf = __half22float2(kk);
            float2 vf = __half22float2(vv);

            float ksum = kf.x + kf.y, ksq = kf.x * kf.x + kf.y * kf.y;
            float vsum = vf.x + vf.y, vsq = vf.x * vf.x + vf.y * vf.y;
#pragma unroll
            for (int o = 16; o > 0; o >>= 1) {
                ksum += __shfl_xor_sync(0xffffffffu, ksum, o);
                ksq  += __shfl_xor_sync(0xffffffffu, ksq, o);
                vsum += __shfl_xor_sync(0xffffffffu, vsum, o);
                vsq  += __shfl_xor_sync(0xffffffffu, vsq, o);
            }
            float kmu = ksum * (1.f / 64.f);
            float kvar = ksq * (1.f / 64.f) - kmu * kmu;
            float krs = rsqrtf(kvar + 1e-6f);
            float vmu = vsum * (1.f / 64.f);
            float vvar = vsq * (1.f / 64.f) - vmu * vmu;
            float vrs = rsqrtf(vvar + 1e-6f);

            float nk0 = (kf.x - kmu) * krs * sks[2 * lane]     + skb[2 * lane];
            float nk1 = (kf.y - kmu) * krs * sks[2 * lane + 1] + skb[2 * lane + 1];
            float nv0 = (vf.x - vmu) * vrs * svs[2 * lane]     + svb[2 * lane];
            float nv1 = (vf.y - vmu) * vrs * svs[2 * lane + 1] + svb[2 * lane + 1];

            *reinterpret_cast<__half2*>(&ksh[r][2 * lane]) = __floats2half2_rn(nk0, nk1);
            *reinterpret_cast<__half2*>(&vsh[r][2 * lane]) = __floats2half2_rn(nv0, nv1);
        }
        __syncthreads();

        uint32_t a[4], bq0[4], bq1[4];
        ldm4t(a, aaddr);
        ldm4t(bq0, baddr0);
        ldm4t(bq1, baddr1);
        uint32_t bfr[4][2] = {{bq0[0], bq0[1]}, {bq0[2], bq0[3]},
                              {bq1[0], bq1[1]}, {bq1[2], bq1[3]}};
#pragma unroll
        for (int nf = 0; nf < 4; ++nf)
            mma16816(acc[nf], a, bfr[nf]);
    }

    float* p = gPpart + ((long)chunk * 64 + bh) * 4096;
    const int lrow = lane >> 2;
    const int lcol = (lane & 3) * 2;
#pragma unroll
    for (int nf = 0; nf < 4; ++nf) {
        int e = e0 + nf * 8 + lcol;
        *reinterpret_cast<float2*>(p + (d0 + lrow) * 64 + e) =
            make_float2(acc[nf][0], acc[nf][1]);
        *reinterpret_cast<float2*>(p + (d0 + lrow + 8) * 64 + e) =
            make_float2(acc[nf][2], acc[nf][3]);
    }
}

// reduce: fp32 p_attn output (required) + fp16 copy for the out GEMM
__global__ void pattn_reduce_kernel(float* __restrict__ pout)
{
    int i = blockIdx.x * blockDim.x + threadIdx.x;
    if (i >= 64 * 4096) return;
    int bh = i >> 12;
    int idx = i & 4095;
    float s = 0.f;
#pragma unroll
    for (int c = 0; c < NCHUNK; c++)
        s += gPpart[((long)c * 64 + bh) * 4096 + idx];
    float r = s * (1.f / 8192.f);
    pout[i] = r;
    gPh[i] = __float2half_rn(r);
}

// ---------------- out = Q @ P  (HMMA, fp16 inputs, fp32 out) -----------------
// Grid (64, 64): 64 n-tiles x 128 rows = 8192 rows per (b,h). 8 warps/block,
// each 16 rows x 64 e. A = Q (non-trans, GEMM-validated), B = P (trans,
// pattn-validated).
__global__ __launch_bounds__(256)
void out_kernel(float* __restrict__ out)
{
    const int bh = blockIdx.y;
    const int b = bh >> 4, h = bh & 15;
    const int n0 = blockIdx.x * 128;

    __shared__ __half psh[64][72];
    __shared__ __half qsh[128][72];

    const int t = threadIdx.x;
    const int warp = t >> 5, lane = t & 31;

    const __half* P = gPh + (size_t)bh * 4096;
    for (int i = t; i < 2048; i += 256) {            // P: 64x64, half2 units
        int d = i >> 5, e2 = (i & 31) * 2;
        *reinterpret_cast<__half2*>(&psh[d][e2]) =
            *reinterpret_cast<const __half2*>(P + d * 64 + e2);
    }
    const size_t base = (size_t)b * (Ss * Ff) + (size_t)h * 524288 + (size_t)n0 * 64;
    for (int i = t; i < 2048; i += 256) {            // Q: 128x64, 4-half units
        int n = i >> 4, d4 = (i & 15) * 4;
        *reinterpret_cast<uint2*>(&qsh[n][d4]) =
            *reinterpret_cast<const uint2*>(gQh + base + (size_t)n * 64 + d4);
    }
    __syncthreads();

    const int arow = (lane & 7) + ((lane >> 3) & 1) * 8;
    const int ao = ((lane >> 4) & 1) * 8;            // halves
    const int brow = (lane & 7) + ((lane >> 3) & 1) * 8;
    const int bo = ((lane >> 4) & 1) * 8;

    float acc[8][4];
#pragma unroll
    for (int i = 0; i < 8; i++)
#pragma unroll
        for (int q = 0; q < 4; q++) acc[i][q] = 0.f;

#pragma unroll
    for (int s = 0; s < 4; ++s) {                    // k = d, 4 steps of 16
        uint32_t a[4];
        ldm4(a, smem_u32(&qsh[warp * 16 + arow][s * 16 + ao]));
        uint32_t bfr[8][2];
#pragma unroll
        for (int g = 0; g < 4; ++g) {                // e groups of 16
            uint32_t r[4];
            ldm4t(r, smem_u32(&psh[s * 16 + brow][g * 16 + bo]));
            bfr[2 * g][0] = r[0]; bfr[2 * g][1] = r[1];
            bfr[2 * g + 1][0] = r[2]; bfr[2 * g + 1][1] = r[3];
        }
#pragma unroll
        for (int nf = 0; nf < 8; ++nf)
            mma16816(acc[nf], a, bfr[nf]);
    }

    const int lrow = lane >> 2;
    const int lcol = (lane & 3) * 2;
#pragma unroll
    for (int nf = 0; nf < 8; ++nf) {
        int e = nf * 8 + lcol;
        *reinterpret_cast<float2*>(out + base + (size_t)(warp * 16 + lrow) * 64 + e) =
            make_float2(acc[nf][0], acc[nf][1]);
        *reinterpret_cast<float2*>(out + base + (size_t)(warp * 16 + lrow + 8) * 64 + e) =
            make_float2(acc[nf][2], acc[nf][3]);
    }
}

// ---------------- launch ----------------------------------------------------
extern "C" void kernel_launch(void* const* d_in, const int* in_sizes, int n_in,
                              void* d_out, int out_size)
{
    (void)in_sizes; (void)n_in; (void)out_size;
    const float* query = (const float*)d_in[0];
    const float* key   = (const float*)d_in[1];
    const float* value = (const float*)d_in[2];
    const float* Wq    = (const float*)d_in[3];
    const float* Wk    = (const float*)d_in[4];
    const float* Wv    = (const float*)d_in[5];
    const float* lnk_s = (const float*)d_in[6];
    const float* lnk_b = (const float*)d_in[7];
    const float* lnv_s = (const float*)d_in[8];
    const float* lnv_b = (const float*)d_in[9];

    float* out = (float*)d_out;
    float* pout = out + QELEMS;

    cudaFuncSetAttribute(gemm_mma_kernel, cudaFuncAttributeMaxDynamicSharedMemorySize,
                         3 * STAGE + 1024);

    convert_A_kernel<<<dim3(16384, 3), 256>>>(query, key, value);
    convert_W_kernel<<<dim3(32, 32, 3), 256>>>(Wq, Wk, Wv);

    gemm_mma_kernel<<<dim3(8, 256, 3), 256, 3 * STAGE + 1024>>>();

    dim3 pgrid(64, NCHUNK);
    pattn_partial_kernel<<<pgrid, 256>>>(lnk_s, lnk_b, lnv_s, lnv_b);
    pattn_reduce_kernel<<<(64 * 4096 + 255) / 256, 256>>>(pout);

    out_kernel<<<dim3(64, 64), 256>>>(out);
}